// round 1
// baseline (speedup 1.0000x reference)
#include <cuda_runtime.h>
#include <math.h>

#define BB_ 32
#define T_ 128
#define D_ 128
#define H_ 132
#define HP_ 144
#define O_ 64
#define K1_ 256
#define RSTR 132

// Scratch (device globals: the sanctioned no-alloc scratch path)
__device__ float g_M[T_ * T_ * BB_ * D_];   // [t][s][bb][d], 256 MB
__device__ float g_W1p[K1_ * HP_];
__device__ float g_W2p[HP_ * HP_];
__device__ float g_W3p[HP_ * O_];
__device__ float g_b1p[HP_];
__device__ float g_b2p[HP_];
__device__ float g_b3p[O_];

typedef unsigned long long ull;

__device__ __forceinline__ ull fma2(ull a, ull b, ull c) {
    ull r;
    asm("fma.rn.f32x2 %0, %1, %2, %3;" : "=l"(r) : "l"(a), "l"(b), "l"(c));
    return r;
}
__device__ __forceinline__ ull dup2(float v) {
    ull r;
    asm("mov.b64 %0, {%1, %1};" : "=l"(r) : "f"(v));
    return r;
}
__device__ __forceinline__ float2 unpk(ull x) {
    float2 r;
    asm("mov.b64 {%0, %1}, %2;" : "=f"(r.x), "=f"(r.y) : "l"(x));
    return r;
}
__device__ __forceinline__ ull pk(float x, float y) {
    ull r;
    asm("mov.b64 %0, {%1, %2};" : "=l"(r) : "f"(x), "f"(y));
    return r;
}

// ---------------- prep: zero-padded weights (H=132 -> HP=144) ----------------
__global__ void prep_weights_kernel(const float* __restrict__ W1, const float* __restrict__ b1,
                                    const float* __restrict__ W2, const float* __restrict__ b2,
                                    const float* __restrict__ W3, const float* __restrict__ b3) {
    int i = blockIdx.x * blockDim.x + threadIdx.x;
    if (i < K1_ * HP_) { int k = i / HP_, c = i - k * HP_; g_W1p[i] = (c < H_) ? W1[k * H_ + c] : 0.f; }
    if (i < HP_ * HP_) { int k = i / HP_, c = i - k * HP_; g_W2p[i] = (k < H_ && c < H_) ? W2[k * H_ + c] : 0.f; }
    if (i < HP_ * O_)  { int k = i / O_,  c = i - k * O_;  g_W3p[i] = (k < H_) ? W3[k * O_ + c] : 0.f; }
    if (i < HP_) { g_b1p[i] = (i < H_) ? b1[i] : 0.f; g_b2p[i] = (i < H_) ? b2[i] : 0.f; }
    if (i < O_)  { g_b3p[i] = b3[i]; }
}

// ---------------- windowed cummax: M[t][s][bb][d] = max(P[bb, t..s, d]) ----------------
__global__ void compute_M_kernel(const float* __restrict__ P) {
    int idx = blockIdx.x * blockDim.x + threadIdx.x;   // t*4096 + bb*128 + d
    int t = idx >> 12;
    int bb = (idx >> 7) & 31;
    int d = idx & 127;
    const float* Pp = P + bb * (T_ * D_) + d;
    float run = Pp[t * D_];
    #pragma unroll 4
    for (int s = t; s < T_; ++s) {
        run = fmaxf(run, Pp[s * D_]);
        g_M[((t * T_ + s) * BB_ + bb) * D_ + d] = run;
    }
}

__global__ void init_out_kernel(float* out) {
    int i = blockIdx.x * blockDim.x + threadIdx.x;
    if (i < BB_ * T_ * O_) out[i] = 0.f;
}

// ---------------- main: per-(t, 4-s chunk) 128-row fused MLP + max reduce ----------------
// SMEM layout:
//   sX:   256 x 132 floats (feature tile, k-major; reused as h1/h2 144x132)
//   sW:   16 x 144 ull    (weight K-slice, value duplicated into both f32x2 halves)
//   sRed: 32 x 64 ints    (per-(bb,o) running max, float bits)
#define SX_BYTES   (K1_ * RSTR * 4)        // 135168
#define SW_BYTES   (16 * HP_ * 8)          // 18432
#define SRED_BYTES (BB_ * O_ * 4)          // 8192
#define SMEM_TOTAL (SX_BYTES + SW_BYTES + SRED_BYTES)

__global__ void __launch_bounds__(256, 1)
mlp_main_kernel(const float* __restrict__ P, float* __restrict__ out) {
    const int t = blockIdx.y;
    const int c = blockIdx.x;
    const int nch = (T_ - t + 3) >> 2;
    if (c >= nch) return;
    const int s0 = t + 4 * c;

    extern __shared__ unsigned char smraw[];
    float* sX  = (float*)smraw;
    ull*   sW  = (ull*)(smraw + SX_BYTES);
    int*   sRed = (int*)(smraw + SX_BYTES + SW_BYTES);

    const int tid = threadIdx.x;
    const int ty = tid >> 4, tx = tid & 15;
    const int r0 = ty * 8;

    for (int i = tid; i < BB_ * O_; i += 256) sRed[i] = 0;

    // Build transposed feature tile: rows r = sl*32+bb (s = s0+sl), cols k:
    //   k in [0,128)   = M[t, s, bb, k]
    //   k in [128,256) = P[bb, s, k-128]
    for (int i = tid; i < 128 * 128; i += 256) {
        int r = i >> 7;
        int d = i & 127;
        int sl = r >> 5, bb = r & 31;
        int s = s0 + sl; s = (s < T_) ? s : (T_ - 1);   // clamp; invalid rows excluded later
        sX[d * RSTR + r]         = g_M[((t * T_ + s) * BB_ + bb) * D_ + d];
        sX[(128 + d) * RSTR + r] = P[(bb * T_ + s) * D_ + d];
    }
    __syncthreads();

    // ---------------- Stage A: h1 = relu(X @ W1p + b1p), K=256, 144 cols ----------------
    const int cA = tx * 9;
    ull acc[36];
    #pragma unroll
    for (int i = 0; i < 36; i++) acc[i] = 0ull;

    float wv[9];
    #pragma unroll
    for (int j = 0; j < 9; j++) {
        int i = tid + 256 * j;
        int kk = i / 144, cc = i - kk * 144;
        wv[j] = g_W1p[kk * HP_ + cc];
    }
    for (int k0 = 0; k0 < 256; k0 += 16) {
        __syncthreads();
        #pragma unroll
        for (int j = 0; j < 9; j++) {
            int i = tid + 256 * j;
            int kk = i / 144, cc = i - kk * 144;
            sW[kk * HP_ + cc] = dup2(wv[j]);
        }
        __syncthreads();
        if (k0 + 16 < 256) {
            #pragma unroll
            for (int j = 0; j < 9; j++) {
                int i = tid + 256 * j;
                int kk = i / 144, cc = i - kk * 144;
                wv[j] = g_W1p[(k0 + 16 + kk) * HP_ + cc];
            }
        }
        #pragma unroll
        for (int k = 0; k < 16; k++) {
            const ull* xa = (const ull*)(sX + (k0 + k) * RSTR + r0);
            ull a0 = xa[0], a1 = xa[1], a2 = xa[2], a3 = xa[3];
            const ull* wb = sW + k * HP_ + cA;
            #pragma unroll
            for (int j = 0; j < 9; j++) {
                ull w = wb[j];
                acc[j]      = fma2(a0, w, acc[j]);
                acc[9 + j]  = fma2(a1, w, acc[9 + j]);
                acc[18 + j] = fma2(a2, w, acc[18 + j]);
                acc[27 + j] = fma2(a3, w, acc[27 + j]);
            }
        }
    }
    __syncthreads();
    #pragma unroll
    for (int j = 0; j < 9; j++) {
        float bj = g_b1p[cA + j];
        #pragma unroll
        for (int p = 0; p < 4; p++) {
            float2 v = unpk(acc[p * 9 + j]);
            v.x = fmaxf(v.x + bj, 0.f);
            v.y = fmaxf(v.y + bj, 0.f);
            *(ull*)(sX + (cA + j) * RSTR + r0 + 2 * p) = pk(v.x, v.y);
        }
    }

    // ---------------- Stage B: h2 = relu(h1 @ W2p + b2p), K=144, 144 cols ----------------
    #pragma unroll
    for (int i = 0; i < 36; i++) acc[i] = 0ull;
    #pragma unroll
    for (int j = 0; j < 9; j++) {
        int i = tid + 256 * j;
        int kk = i / 144, cc = i - kk * 144;
        wv[j] = g_W2p[kk * HP_ + cc];
    }
    for (int k0 = 0; k0 < 144; k0 += 16) {
        __syncthreads();
        #pragma unroll
        for (int j = 0; j < 9; j++) {
            int i = tid + 256 * j;
            int kk = i / 144, cc = i - kk * 144;
            sW[kk * HP_ + cc] = dup2(wv[j]);
        }
        __syncthreads();
        if (k0 + 16 < 144) {
            #pragma unroll
            for (int j = 0; j < 9; j++) {
                int i = tid + 256 * j;
                int kk = i / 144, cc = i - kk * 144;
                wv[j] = g_W2p[(k0 + 16 + kk) * HP_ + cc];
            }
        }
        #pragma unroll
        for (int k = 0; k < 16; k++) {
            const ull* xa = (const ull*)(sX + (k0 + k) * RSTR + r0);
            ull a0 = xa[0], a1 = xa[1], a2 = xa[2], a3 = xa[3];
            const ull* wb = sW + k * HP_ + cA;
            #pragma unroll
            for (int j = 0; j < 9; j++) {
                ull w = wb[j];
                acc[j]      = fma2(a0, w, acc[j]);
                acc[9 + j]  = fma2(a1, w, acc[9 + j]);
                acc[18 + j] = fma2(a2, w, acc[18 + j]);
                acc[27 + j] = fma2(a3, w, acc[27 + j]);
            }
        }
    }
    __syncthreads();
    #pragma unroll
    for (int j = 0; j < 9; j++) {
        float bj = g_b2p[cA + j];
        #pragma unroll
        for (int p = 0; p < 4; p++) {
            float2 v = unpk(acc[p * 9 + j]);
            v.x = fmaxf(v.x + bj, 0.f);
            v.y = fmaxf(v.y + bj, 0.f);
            *(ull*)(sX + (cA + j) * RSTR + r0 + 2 * p) = pk(v.x, v.y);
        }
    }

    // ---------------- Stage C: y = sigmoid(5*(h2 @ W3p + b3)), K=144, 64 cols ----------------
    const int cC = tx * 4;
    ull acc3[16];
    #pragma unroll
    for (int i = 0; i < 16; i++) acc3[i] = 0ull;
    float wv3[4];
    #pragma unroll
    for (int j = 0; j < 4; j++) {
        int i = tid + 256 * j;
        int kk = i >> 6, cc = i & 63;
        wv3[j] = g_W3p[kk * O_ + cc];
    }
    for (int k0 = 0; k0 < 144; k0 += 16) {
        __syncthreads();
        #pragma unroll
        for (int j = 0; j < 4; j++) {
            int i = tid + 256 * j;
            int kk = i >> 6, cc = i & 63;
            sW[kk * O_ + cc] = dup2(wv3[j]);
        }
        __syncthreads();
        if (k0 + 16 < 144) {
            #pragma unroll
            for (int j = 0; j < 4; j++) {
                int i = tid + 256 * j;
                int kk = i >> 6, cc = i & 63;
                wv3[j] = g_W3p[(k0 + 16 + kk) * O_ + cc];
            }
        }
        #pragma unroll
        for (int k = 0; k < 16; k++) {
            const ull* xa = (const ull*)(sX + (k0 + k) * RSTR + r0);
            ull a0 = xa[0], a1 = xa[1], a2 = xa[2], a3 = xa[3];
            const ull* wb = sW + k * O_ + cC;
            #pragma unroll
            for (int j = 0; j < 4; j++) {
                ull w = wb[j];
                acc3[j]      = fma2(a0, w, acc3[j]);
                acc3[4 + j]  = fma2(a1, w, acc3[4 + j]);
                acc3[8 + j]  = fma2(a2, w, acc3[8 + j]);
                acc3[12 + j] = fma2(a3, w, acc3[12 + j]);
            }
        }
    }

    // epilogue: sigmoid + per-(bb,o) smem max (skip rows with s >= T)
    {
        int s = s0 + (ty >> 2);
        if (s < T_) {
            #pragma unroll
            for (int j = 0; j < 4; j++) {
                float bj = g_b3p[cC + j];
                #pragma unroll
                for (int p = 0; p < 4; p++) {
                    float2 v = unpk(acc3[p * 4 + j]);
                    float y0 = 1.f / (1.f + expf(-5.f * (v.x + bj)));
                    float y1 = 1.f / (1.f + expf(-5.f * (v.y + bj)));
                    int bb0 = (ty & 3) * 8 + 2 * p;
                    atomicMax(&sRed[bb0 * O_ + cC + j], __float_as_int(y0));
                    atomicMax(&sRed[(bb0 + 1) * O_ + cC + j], __float_as_int(y1));
                }
            }
        }
    }
    __syncthreads();
    // fold chunk max into global output (positive floats: int atomicMax is exact)
    for (int i = tid; i < BB_ * O_; i += 256) {
        int bb = i >> 6, o = i & 63;
        atomicMax((int*)(out + (bb * T_ + t) * O_ + o), sRed[i]);
    }
}

// ---------------- launch ----------------
extern "C" void kernel_launch(void* const* d_in, const int* in_sizes, int n_in,
                              void* d_out, int out_size) {
    const float* P  = (const float*)d_in[0];
    const float* W1 = (const float*)d_in[1];
    const float* b1 = (const float*)d_in[2];
    const float* W2 = (const float*)d_in[3];
    const float* b2 = (const float*)d_in[4];
    const float* W3 = (const float*)d_in[5];
    const float* b3 = (const float*)d_in[6];
    float* out = (float*)d_out;

    cudaFuncSetAttribute(mlp_main_kernel, cudaFuncAttributeMaxDynamicSharedMemorySize, SMEM_TOTAL);

    prep_weights_kernel<<<(K1_ * HP_ + 255) / 256, 256>>>(W1, b1, W2, b2, W3, b3);
    compute_M_kernel<<<(T_ * BB_ * D_) / 256, 256>>>(P);
    init_out_kernel<<<(BB_ * T_ * O_ + 255) / 256, 256>>>(out);
    mlp_main_kernel<<<dim3(32, 128), 256, SMEM_TOTAL>>>(P, out);
}

// round 3
// speedup vs baseline: 1.2006x; 1.2006x over previous
#include <cuda_runtime.h>
#include <cuda_bf16.h>
#include <math.h>
#include <stdint.h>

#define BB_ 32
#define T_ 128
#define D_ 128
#define H_ 132
#define O_ 64

#define NSTRIDE 36                    // bf16 per n-row in W chunk (72B, conflict-free frags)
#define CHUNK1_E (144 * NSTRIDE)      // 5184 bf16 = 2592 words (N=144 chunk)
#define CHUNK3_E (64 * NSTRIDE)       // 2304 bf16 = 1152 words (N=64 chunk)
#define CHUNKB   10368                // max chunk bytes

// ---------------- SMEM layout ----------------
#define OFF_XH  0
#define OFF_XL  65536
#define OFF_W   131072                // 2 x CHUNKB = 20736
#define OFF_B1  151808
#define OFF_B2  152384
#define OFF_B3  152960
#define OFF_RED 153216                // 2048 ints
#define SMEM_TOTAL 161408

// ---------------- device scratch ----------------
__device__ float g_pre[T_ * 32 * BB_ * D_];          // [t][c][bb][d] prefix max over [t, t+4(c+1))
__device__ __nv_bfloat16 g_W1s[16 * CHUNK1_E];       // [kstep][n][half(hi/lo)][16k] (+4 pad)
__device__ __nv_bfloat16 g_W2s[9 * CHUNK1_E];
__device__ __nv_bfloat16 g_W3s[9 * CHUNK3_E];

// ---------------- mma ----------------
__device__ __forceinline__ void mma_bf16(float d[4], const uint32_t a[4], const uint32_t b[2]) {
    asm volatile("mma.sync.aligned.m16n8k16.row.col.f32.bf16.bf16.f32 "
                 "{%0,%1,%2,%3}, {%4,%5,%6,%7}, {%8,%9}, {%0,%1,%2,%3};"
                 : "+f"(d[0]), "+f"(d[1]), "+f"(d[2]), "+f"(d[3])
                 : "r"(a[0]), "r"(a[1]), "r"(a[2]), "r"(a[3]), "r"(b[0]), "r"(b[1]));
}

// ---------------- prep: hi/lo split weights in frag-friendly layout ----------------
__global__ void prep_weights(const float* __restrict__ W1, const float* __restrict__ W2,
                             const float* __restrict__ W3) {
    int i = blockIdx.x * blockDim.x + threadIdx.x;
    if (i < 16 * CHUNK1_E) {
        int ks = i / CHUNK1_E, r = i % CHUNK1_E;
        int n = r / NSTRIDE, q = r % NSTRIDE;
        int half = q >> 4, kk = q & 15;
        __nv_bfloat16 o = __float2bfloat16(0.f);
        if (half < 2 && n < H_) {
            float w = W1[(ks * 16 + kk) * H_ + n];
            __nv_bfloat16 hi = __float2bfloat16(w);
            o = half ? __float2bfloat16(w - __bfloat162float(hi)) : hi;
        }
        g_W1s[i] = o;
    }
    if (i < 9 * CHUNK1_E) {
        int ks = i / CHUNK1_E, r = i % CHUNK1_E;
        int n = r / NSTRIDE, q = r % NSTRIDE;
        int half = q >> 4, kk = q & 15;
        int k = ks * 16 + kk;
        __nv_bfloat16 o = __float2bfloat16(0.f);
        if (half < 2 && n < H_ && k < H_) {
            float w = W2[k * H_ + n];
            __nv_bfloat16 hi = __float2bfloat16(w);
            o = half ? __float2bfloat16(w - __bfloat162float(hi)) : hi;
        }
        g_W2s[i] = o;
    }
    if (i < 9 * CHUNK3_E) {
        int ks = i / CHUNK3_E, r = i % CHUNK3_E;
        int n = r / NSTRIDE, q = r % NSTRIDE;
        int half = q >> 4, kk = q & 15;
        int k = ks * 16 + kk;
        __nv_bfloat16 o = __float2bfloat16(0.f);
        if (half < 2 && k < H_) {
            float w = W3[k * O_ + n];
            __nv_bfloat16 hi = __float2bfloat16(w);
            o = half ? __float2bfloat16(w - __bfloat162float(hi)) : hi;
        }
        g_W3s[i] = o;
    }
}

// ---------------- prefix max at 4-chunk boundaries ----------------
__global__ void compute_pre_kernel(const float* __restrict__ P) {
    int idx = blockIdx.x * blockDim.x + threadIdx.x;
    int t = idx >> 12, bb = (idx >> 7) & 31, d = idx & 127;
    const float* Pp = P + bb * (T_ * D_) + d;
    float run = -3.4e38f;
    for (int s = t; s < T_; ++s) {
        run = fmaxf(run, Pp[s * D_]);
        int m = s - t + 1;
        if ((m & 3) == 0) {
            int ci = (m >> 2) - 1;
            if (ci < 32) g_pre[((t * 32 + ci) * BB_ + bb) * D_ + d] = run;
        }
    }
}

__global__ void init_out_kernel(float* out) {
    int i = blockIdx.x * blockDim.x + threadIdx.x;
    if (i < BB_ * T_ * O_) out[i] = 0.f;
}

// ---------------- GEMM stage: streamed W chunks, 3-MMA split ----------------
template <int K16, int NT>
__device__ __forceinline__ void gemm_stage(const __nv_bfloat16* __restrict__ Wg,
                                           int chunk_words, char* smem,
                                           float (*acc)[4], int m0, int nbase, int tid) {
    char* xh = smem + OFF_XH;
    char* xl = smem + OFF_XL;
    char* wbuf = smem + OFF_W;
    const uint32_t* Wg32 = (const uint32_t*)Wg;
    {
        uint32_t* dst = (uint32_t*)wbuf;
        for (int i = tid; i < chunk_words; i += 256) dst[i] = Wg32[i];
    }
    __syncthreads();
    const int lane = tid & 31;
    const int grp = lane >> 2;
    const int k4 = (lane & 3) * 4;
    #pragma unroll 1
    for (int k = 0; k < K16; ++k) {
        if (k + 1 < K16) {
            const uint32_t* src = Wg32 + (size_t)(k + 1) * chunk_words;
            uint32_t* dst = (uint32_t*)(wbuf + ((k + 1) & 1) * CHUNKB);
            for (int i = tid; i < chunk_words; i += 256) dst[i] = src[i];
        }
        char* wb = wbuf + (k & 1) * CHUNKB;
        uint32_t ah[2][4], al[2][4];
        #pragma unroll
        for (int mt = 0; mt < 2; ++mt) {
            const char* ph = xh + k * 4096 + (m0 + mt * 16 + grp) * 32 + k4;
            ah[mt][0] = *(const uint32_t*)(ph);
            ah[mt][1] = *(const uint32_t*)(ph + 256);
            ah[mt][2] = *(const uint32_t*)(ph + 16);
            ah[mt][3] = *(const uint32_t*)(ph + 272);
            const char* pl = xl + k * 4096 + (m0 + mt * 16 + grp) * 32 + k4;
            al[mt][0] = *(const uint32_t*)(pl);
            al[mt][1] = *(const uint32_t*)(pl + 256);
            al[mt][2] = *(const uint32_t*)(pl + 16);
            al[mt][3] = *(const uint32_t*)(pl + 272);
        }
        #pragma unroll
        for (int j = 0; j < NT; ++j) {
            int n = nbase + j * 8 + grp;
            const char* bp = wb + n * 72 + k4;
            uint32_t bh[2] = { *(const uint32_t*)bp, *(const uint32_t*)(bp + 16) };
            uint32_t bl[2] = { *(const uint32_t*)(bp + 32), *(const uint32_t*)(bp + 48) };
            mma_bf16(acc[0 * NT + j], ah[0], bh);
            mma_bf16(acc[1 * NT + j], ah[1], bh);
            mma_bf16(acc[0 * NT + j], al[0], bh);
            mma_bf16(acc[1 * NT + j], al[1], bh);
            mma_bf16(acc[0 * NT + j], ah[0], bl);
            mma_bf16(acc[1 * NT + j], ah[1], bl);
        }
        __syncthreads();
    }
}

// ---------------- relu epilogue: write hi/lo X tiles for next stage ----------------
__device__ __forceinline__ void epi_relu(char* smem, float (*acc)[4], const float* bias,
                                         int m0, int nbase, int lane) {
    char* xh = smem + OFF_XH;
    char* xl = smem + OFF_XL;
    const int grp = lane >> 2;
    const int c0 = 2 * (lane & 3);
    #pragma unroll
    for (int mt = 0; mt < 2; ++mt)
    #pragma unroll
    for (int j = 0; j < 9; ++j) {
        int n0 = nbase + j * 8 + c0;
        float bv0 = bias[n0], bv1 = bias[n0 + 1];
        int ks = n0 >> 4, kk = n0 & 15;
        #pragma unroll
        for (int rp = 0; rp < 2; ++rp) {
            int row = m0 + mt * 16 + grp + rp * 8;
            float v0 = fmaxf(acc[mt * 9 + j][rp * 2 + 0] + bv0, 0.f);
            float v1 = fmaxf(acc[mt * 9 + j][rp * 2 + 1] + bv1, 0.f);
            __nv_bfloat16 h0 = __float2bfloat16(v0), h1 = __float2bfloat16(v1);
            __nv_bfloat162 hp; hp.x = h0; hp.y = h1;
            __nv_bfloat162 lp;
            lp.x = __float2bfloat16(v0 - __bfloat162float(h0));
            lp.y = __float2bfloat16(v1 - __bfloat162float(h1));
            int off = ks * 4096 + row * 32 + kk * 2;
            *(__nv_bfloat162*)(xh + off) = hp;
            *(__nv_bfloat162*)(xl + off) = lp;
        }
    }
}

// ---------------- main ----------------
__global__ void __launch_bounds__(256, 1)
mlp_main_kernel(const float* __restrict__ P,
                const float* __restrict__ b1, const float* __restrict__ b2,
                const float* __restrict__ b3, float* __restrict__ out) {
    const int t = blockIdx.y;
    const int c = blockIdx.x;
    const int nch = (T_ - t + 3) >> 2;
    if (c >= nch) return;
    const int s0 = t + 4 * c;

    extern __shared__ char smem[];
    const int tid = threadIdx.x;
    float* sB1 = (float*)(smem + OFF_B1);
    float* sB2 = (float*)(smem + OFF_B2);
    float* sB3 = (float*)(smem + OFF_B3);
    int* sRed = (int*)(smem + OFF_RED);

    for (int i = tid; i < 144; i += 256) {
        sB1[i] = (i < H_) ? b1[i] : 0.f;
        sB2[i] = (i < H_) ? b2[i] : 0.f;
    }
    if (tid < 64) sB3[tid] = b3[tid];
    for (int i = tid; i < BB_ * O_; i += 256) sRed[i] = 0;

    // feature build: rows r = sl*32+bb; K cols [0,128)=running max, [128,256)=P
    {
        int d = tid & 127, half = tid >> 7;
        char* xh = smem + OFF_XH;
        char* xl = smem + OFF_XL;
        int ksM = d >> 4, kk = d & 15;
        int offM = ksM * 4096 + kk * 2;
        int offP = (8 + ksM) * 4096 + kk * 2;
        for (int bb = half * 16; bb < half * 16 + 16; ++bb) {
            float run = (c > 0) ? g_pre[((t * 32 + (c - 1)) * BB_ + bb) * D_ + d] : -3.4e38f;
            #pragma unroll
            for (int sl = 0; sl < 4; ++sl) {
                int s = s0 + sl;
                float pv = 0.f;
                if (s < T_) { pv = P[(bb * T_ + s) * D_ + d]; run = fmaxf(run, pv); }
                int row = sl * 32 + bb;
                __nv_bfloat16 hm = __float2bfloat16(run);
                *(__nv_bfloat16*)(xh + offM + row * 32) = hm;
                *(__nv_bfloat16*)(xl + offM + row * 32) = __float2bfloat16(run - __bfloat162float(hm));
                __nv_bfloat16 hq = __float2bfloat16(pv);
                *(__nv_bfloat16*)(xh + offP + row * 32) = hq;
                *(__nv_bfloat16*)(xl + offP + row * 32) = __float2bfloat16(pv - __bfloat162float(hq));
            }
        }
    }
    __syncthreads();

    const int wid = tid >> 5, lane = tid & 31;
    const int m0 = (wid & 3) * 32;
    const int nh = wid >> 2;

    float acc[18][4];

    // Stage A: K=256, N=144
    #pragma unroll
    for (int i = 0; i < 18; ++i) { acc[i][0] = acc[i][1] = acc[i][2] = acc[i][3] = 0.f; }
    gemm_stage<16, 9>(g_W1s, CHUNK1_E / 2, smem, acc, m0, nh * 72, tid);
    epi_relu(smem, acc, sB1, m0, nh * 72, lane);
    __syncthreads();

    // Stage B: K=144, N=144
    #pragma unroll
    for (int i = 0; i < 18; ++i) { acc[i][0] = acc[i][1] = acc[i][2] = acc[i][3] = 0.f; }
    gemm_stage<9, 9>(g_W2s, CHUNK1_E / 2, smem, acc, m0, nh * 72, tid);
    epi_relu(smem, acc, sB2, m0, nh * 72, lane);
    __syncthreads();

    // Stage C: K=144, N=64
    #pragma unroll
    for (int i = 0; i < 8; ++i) { acc[i][0] = acc[i][1] = acc[i][2] = acc[i][3] = 0.f; }
    gemm_stage<9, 4>(g_W3s, CHUNK3_E / 2, smem, acc, m0, nh * 32, tid);

    // final epilogue: sigmoid + max reduce
    {
        const int grp = lane >> 2;
        const int c0 = 2 * (lane & 3);
        #pragma unroll
        for (int mt = 0; mt < 2; ++mt)
        #pragma unroll
        for (int rp = 0; rp < 2; ++rp) {
            int row = m0 + mt * 16 + grp + rp * 8;
            int sl = row >> 5, bb = row & 31;
            if (s0 + sl < T_) {
                #pragma unroll
                for (int j = 0; j < 4; ++j) {
                    int n0 = nh * 32 + j * 8 + c0;
                    float y0 = 1.f / (1.f + __expf(-5.f * (acc[mt * 4 + j][rp * 2 + 0] + sB3[n0])));
                    float y1 = 1.f / (1.f + __expf(-5.f * (acc[mt * 4 + j][rp * 2 + 1] + sB3[n0 + 1])));
                    atomicMax(&sRed[bb * O_ + n0], __float_as_int(y0));
                    atomicMax(&sRed[bb * O_ + n0 + 1], __float_as_int(y1));
                }
            }
        }
    }
    __syncthreads();
    for (int i = tid; i < BB_ * O_; i += 256) {
        int bb = i >> 6, o = i & 63;
        atomicMax((int*)(out + (bb * T_ + t) * O_ + o), sRed[i]);
    }
}

// ---------------- launch ----------------
extern "C" void kernel_launch(void* const* d_in, const int* in_sizes, int n_in,
                              void* d_out, int out_size) {
    const float* P  = (const float*)d_in[0];
    const float* W1 = (const float*)d_in[1];
    const float* b1 = (const float*)d_in[2];
    const float* W2 = (const float*)d_in[3];
    const float* b2 = (const float*)d_in[4];
    const float* W3 = (const float*)d_in[5];
    const float* b3 = (const float*)d_in[6];
    float* out = (float*)d_out;

    cudaFuncSetAttribute(mlp_main_kernel, cudaFuncAttributeMaxDynamicSharedMemorySize, SMEM_TOTAL);

    prep_weights<<<(16 * CHUNK1_E + 255) / 256, 256>>>(W1, W2, W3);
    compute_pre_kernel<<<(T_ * BB_ * D_) / 256, 256>>>(P);
    init_out_kernel<<<(BB_ * T_ * O_ + 255) / 256, 256>>>(out);
    mlp_main_kernel<<<dim3(32, T_), 256, SMEM_TOTAL>>>(P, b1, b2, b3, out);
}

// round 4
// speedup vs baseline: 1.9654x; 1.6370x over previous
#include <cuda_runtime.h>
#include <cuda_bf16.h>
#include <math.h>
#include <stdint.h>

#define BB_ 32
#define T_ 128
#define D_ 128
#define H_ 132
#define O_ 64

#define NSTRIDE 36                    // bf16 per n-row (72B): [k0..15 hi][k0..15 lo][4 pad]
#define WBUF 11520                    // one k-step chunk, N=160 padded (160*72)
#define CHUNKC 4608                   // stage-C chunk (64*72)

// ---------------- SMEM layout ----------------
#define OFF_XH  0                     // 16 ksteps x 64 rows x 32B = 32768
#define OFF_XL  32768
#define OFF_W   65536                 // 3 x WBUF = 34560
#define OFF_B1  100096                // 160 floats
#define OFF_B2  100736
#define OFF_B3  101376                // 64 floats
#define OFF_RED 101632                // 2048 ints
#define SMEM_TOTAL 109824

// ---------------- device scratch ----------------
__device__ float g_pre2[T_ * 64 * BB_ * D_];         // [t][c][bb][d] prefix max over [t, t+2(c+1))
__device__ __nv_bfloat16 g_W1s[16 * 160 * NSTRIDE];  // [kstep][n][36]
__device__ __nv_bfloat16 g_W2s[9 * 160 * NSTRIDE];
__device__ __nv_bfloat16 g_W3s[9 * 64 * NSTRIDE];

// ---------------- asm helpers ----------------
__device__ __forceinline__ void mma_bf16(float d[4], const uint32_t a[4], const uint32_t b[2]) {
    asm volatile("mma.sync.aligned.m16n8k16.row.col.f32.bf16.bf16.f32 "
                 "{%0,%1,%2,%3}, {%4,%5,%6,%7}, {%8,%9}, {%0,%1,%2,%3};"
                 : "+f"(d[0]), "+f"(d[1]), "+f"(d[2]), "+f"(d[3])
                 : "r"(a[0]), "r"(a[1]), "r"(a[2]), "r"(a[3]), "r"(b[0]), "r"(b[1]));
}
__device__ __forceinline__ uint32_t smem_u32(const void* p) {
    uint32_t a;
    asm("{ .reg .u64 t; cvta.to.shared.u64 t, %1; cvt.u32.u64 %0, t; }" : "=r"(a) : "l"(p));
    return a;
}
#define CP16(dst, src) asm volatile("cp.async.ca.shared.global [%0], [%1], 16;" :: "r"(dst), "l"(src) : "memory")
#define CP_COMMIT()    asm volatile("cp.async.commit_group;" ::: "memory")
#define CP_WAIT1()     asm volatile("cp.async.wait_group 1;" ::: "memory")

// X element address with 16B-half swizzle (kills A-frag bank conflicts)
__device__ __forceinline__ int x_off(int ks, int row, int kk) {
    int phys = (kk >> 3) ^ ((row >> 2) & 1);
    return ks * 2048 + row * 32 + phys * 16 + (kk & 7) * 2;
}

// ---------------- prep: hi/lo split weights, N padded to 160 ----------------
__global__ void prep_weights(const float* __restrict__ W1, const float* __restrict__ W2,
                             const float* __restrict__ W3) {
    int i = blockIdx.x * blockDim.x + threadIdx.x;
    if (i < 16 * 160 * NSTRIDE) {
        int ks = i / (160 * NSTRIDE), r = i % (160 * NSTRIDE);
        int n = r / NSTRIDE, q = r % NSTRIDE;
        int half = q >> 4, kk = q & 15;
        __nv_bfloat16 o = __float2bfloat16(0.f);
        if (half < 2 && n < H_) {
            float w = W1[(ks * 16 + kk) * H_ + n];
            __nv_bfloat16 hi = __float2bfloat16(w);
            o = half ? __float2bfloat16(w - __bfloat162float(hi)) : hi;
        }
        g_W1s[i] = o;
    }
    if (i < 9 * 160 * NSTRIDE) {
        int ks = i / (160 * NSTRIDE), r = i % (160 * NSTRIDE);
        int n = r / NSTRIDE, q = r % NSTRIDE;
        int half = q >> 4, kk = q & 15;
        int k = ks * 16 + kk;
        __nv_bfloat16 o = __float2bfloat16(0.f);
        if (half < 2 && n < H_ && k < H_) {
            float w = W2[k * H_ + n];
            __nv_bfloat16 hi = __float2bfloat16(w);
            o = half ? __float2bfloat16(w - __bfloat162float(hi)) : hi;
        }
        g_W2s[i] = o;
    }
    if (i < 9 * 64 * NSTRIDE) {
        int ks = i / (64 * NSTRIDE), r = i % (64 * NSTRIDE);
        int n = r / NSTRIDE, q = r % NSTRIDE;
        int half = q >> 4, kk = q & 15;
        int k = ks * 16 + kk;
        __nv_bfloat16 o = __float2bfloat16(0.f);
        if (half < 2 && k < H_) {
            float w = W3[k * O_ + n];
            __nv_bfloat16 hi = __float2bfloat16(w);
            o = half ? __float2bfloat16(w - __bfloat162float(hi)) : hi;
        }
        g_W3s[i] = o;
    }
}

// ---------------- prefix max at 2-step boundaries ----------------
__global__ void compute_pre_kernel(const float* __restrict__ P) {
    int idx = blockIdx.x * blockDim.x + threadIdx.x;
    int t = idx >> 12, bb = (idx >> 7) & 31, d = idx & 127;
    const float* Pp = P + bb * (T_ * D_) + d;
    float run = -3.4e38f;
    for (int s = t; s < T_; ++s) {
        run = fmaxf(run, Pp[s * D_]);
        int m = s - t + 1;
        if ((m & 1) == 0) {
            int ci = (m >> 1) - 1;
            if (ci < 64) g_pre2[((t * 64 + ci) * BB_ + bb) * D_ + d] = run;
        }
    }
}

__global__ void init_out_kernel(float* out) {
    int i = blockIdx.x * blockDim.x + threadIdx.x;
    if (i < BB_ * T_ * O_) out[i] = 0.f;
}

// ---------------- GEMM stage: cp.async 3-buffer weight stream, split-bf16 MMAs ----------------
template <int K16, int NT>
__device__ __forceinline__ void gemm_stage(const char* __restrict__ Wg, int chunk_bytes,
                                           char* smem, uint32_t su,
                                           float (*acc)[4], int m0, int nbase, int tid) {
    const int lane = tid & 31;
    const int grp = lane >> 2;
    const int k4 = (lane & 3) * 4;
    // prologue: chunks 0, 1
    for (int off = tid * 16; off < chunk_bytes; off += 4096) CP16(su + OFF_W + off, Wg + off);
    CP_COMMIT();
    for (int off = tid * 16; off < chunk_bytes; off += 4096) CP16(su + OFF_W + WBUF + off, Wg + chunk_bytes + off);
    CP_COMMIT();
    #pragma unroll 1
    for (int k = 0; k < K16; ++k) {
        CP_WAIT1();
        __syncthreads();
        if (k + 2 < K16) {
            const char* src = Wg + (size_t)(k + 2) * chunk_bytes;
            uint32_t dst = su + OFF_W + ((k + 2) % 3) * WBUF;
            for (int off = tid * 16; off < chunk_bytes; off += 4096) CP16(dst + off, src + off);
        }
        CP_COMMIT();
        const char* wb = smem + OFF_W + (k % 3) * WBUF;
        uint32_t ah[2][4], al[2][4];
        #pragma unroll
        for (int mt = 0; mt < 2; ++mt) {
            int row = m0 + mt * 16 + grp;
            int swz = (row & 4) ? 16 : 0;
            const char* ph = smem + OFF_XH + k * 2048 + row * 32;
            const char* pl = smem + OFF_XL + k * 2048 + row * 32;
            ah[mt][0] = *(const uint32_t*)(ph + swz + k4);
            ah[mt][1] = *(const uint32_t*)(ph + 256 + swz + k4);
            ah[mt][2] = *(const uint32_t*)(ph + (swz ^ 16) + k4);
            ah[mt][3] = *(const uint32_t*)(ph + 256 + (swz ^ 16) + k4);
            al[mt][0] = *(const uint32_t*)(pl + swz + k4);
            al[mt][1] = *(const uint32_t*)(pl + 256 + swz + k4);
            al[mt][2] = *(const uint32_t*)(pl + (swz ^ 16) + k4);
            al[mt][3] = *(const uint32_t*)(pl + 256 + (swz ^ 16) + k4);
        }
        #pragma unroll
        for (int j = 0; j < NT; ++j) {
            int n = nbase + j * 8 + grp;
            const char* bp = wb + n * 72 + k4;
            uint32_t bh[2] = { *(const uint32_t*)bp, *(const uint32_t*)(bp + 16) };
            uint32_t bl[2] = { *(const uint32_t*)(bp + 32), *(const uint32_t*)(bp + 48) };
            mma_bf16(acc[0 * NT + j], ah[0], bh);
            mma_bf16(acc[1 * NT + j], ah[1], bh);
            mma_bf16(acc[0 * NT + j], al[0], bh);
            mma_bf16(acc[1 * NT + j], al[1], bh);
            mma_bf16(acc[0 * NT + j], ah[0], bl);
            mma_bf16(acc[1 * NT + j], ah[1], bl);
        }
    }
}

// ---------------- relu epilogue: write hi/lo X tiles for next stage ----------------
__device__ __forceinline__ void epi_relu(char* smem, float (*acc)[4], const float* bias,
                                         int m0, int nbase, int lane) {
    char* xh = smem + OFF_XH;
    char* xl = smem + OFF_XL;
    const int grp = lane >> 2;
    const int c0 = 2 * (lane & 3);
    #pragma unroll
    for (int mt = 0; mt < 2; ++mt)
    #pragma unroll
    for (int j = 0; j < 5; ++j) {
        int n0 = nbase + j * 8 + c0;
        if (n0 >= 144) continue;
        float bv0 = bias[n0], bv1 = bias[n0 + 1];
        int ks = n0 >> 4, kk = n0 & 15;
        #pragma unroll
        for (int rp = 0; rp < 2; ++rp) {
            int row = m0 + mt * 16 + grp + rp * 8;
            float v0 = fmaxf(acc[mt * 5 + j][rp * 2 + 0] + bv0, 0.f);
            float v1 = fmaxf(acc[mt * 5 + j][rp * 2 + 1] + bv1, 0.f);
            __nv_bfloat16 h0 = __float2bfloat16(v0), h1 = __float2bfloat16(v1);
            __nv_bfloat162 hp; hp.x = h0; hp.y = h1;
            __nv_bfloat162 lp;
            lp.x = __float2bfloat16(v0 - __bfloat162float(h0));
            lp.y = __float2bfloat16(v1 - __bfloat162float(h1));
            int off = x_off(ks, row, kk);
            *(__nv_bfloat162*)(xh + off) = hp;
            *(__nv_bfloat162*)(xl + off) = lp;
        }
    }
}

// ---------------- main ----------------
__global__ void __launch_bounds__(256, 2)
mlp_main_kernel(const float* __restrict__ P,
                const float* __restrict__ b1, const float* __restrict__ b2,
                const float* __restrict__ b3, float* __restrict__ out) {
    const int t = blockIdx.y;
    const int c = blockIdx.x;
    const int nch = (T_ - t + 1) >> 1;
    if (c >= nch) return;
    const int s0 = t + 2 * c;

    extern __shared__ char smem[];
    uint32_t su = smem_u32(smem);
    const int tid = threadIdx.x;
    float* sB1 = (float*)(smem + OFF_B1);
    float* sB2 = (float*)(smem + OFF_B2);
    float* sB3 = (float*)(smem + OFF_B3);
    int* sRed = (int*)(smem + OFF_RED);

    for (int i = tid; i < 160; i += 256) {
        sB1[i] = (i < H_) ? b1[i] : 0.f;
        sB2[i] = (i < H_) ? b2[i] : 0.f;
    }
    if (tid < 64) sB3[tid] = b3[tid];
    for (int i = tid; i < BB_ * O_; i += 256) sRed[i] = 0;

    // feature build: rows r = sl*32+bb (sl in 0..1); K cols [0,128)=running max, [128,256)=P
    {
        int d = tid & 127, half = tid >> 7;
        char* xh = smem + OFF_XH;
        char* xl = smem + OFF_XL;
        int ksM = d >> 4, kk = d & 15;
        for (int bb = half * 16; bb < half * 16 + 16; ++bb) {
            float run = (c > 0) ? g_pre2[((t * 64 + (c - 1)) * BB_ + bb) * D_ + d] : -3.4e38f;
            #pragma unroll
            for (int sl = 0; sl < 2; ++sl) {
                int s = s0 + sl;
                float pv = 0.f;
                if (s < T_) { pv = P[(bb * T_ + s) * D_ + d]; run = fmaxf(run, pv); }
                int row = sl * 32 + bb;
                int offM = x_off(ksM, row, kk);
                int offP = x_off(8 + ksM, row, kk);
                __nv_bfloat16 hm = __float2bfloat16(run);
                *(__nv_bfloat16*)(xh + offM) = hm;
                *(__nv_bfloat16*)(xl + offM) = __float2bfloat16(run - __bfloat162float(hm));
                __nv_bfloat16 hq = __float2bfloat16(pv);
                *(__nv_bfloat16*)(xh + offP) = hq;
                *(__nv_bfloat16*)(xl + offP) = __float2bfloat16(pv - __bfloat162float(hq));
            }
        }
    }
    __syncthreads();

    const int wid = tid >> 5, lane = tid & 31;
    const int m0 = (wid & 1) * 32;
    const int nh = wid >> 1;

    float acc[10][4];

    // Stage A: K=256 (16 ksteps), N=160 padded
    #pragma unroll
    for (int i = 0; i < 10; ++i) { acc[i][0] = acc[i][1] = acc[i][2] = acc[i][3] = 0.f; }
    gemm_stage<16, 5>((const char*)g_W1s, WBUF, smem, su, acc, m0, nh * 40, tid);
    __syncthreads();
    epi_relu(smem, acc, sB1, m0, nh * 40, lane);
    __syncthreads();

    // Stage B: K=144 (9 ksteps), N=160 padded
    #pragma unroll
    for (int i = 0; i < 10; ++i) { acc[i][0] = acc[i][1] = acc[i][2] = acc[i][3] = 0.f; }
    gemm_stage<9, 5>((const char*)g_W2s, WBUF, smem, su, acc, m0, nh * 40, tid);
    __syncthreads();
    epi_relu(smem, acc, sB2, m0, nh * 40, lane);
    __syncthreads();

    // Stage C: K=144 (9 ksteps), N=64
    #pragma unroll
    for (int i = 0; i < 4; ++i) { acc[i][0] = acc[i][1] = acc[i][2] = acc[i][3] = 0.f; }
    gemm_stage<9, 2>((const char*)g_W3s, CHUNKC, smem, su, acc, m0, nh * 16, tid);

    // final epilogue: sigmoid + max reduce
    {
        const int grp = lane >> 2;
        const int c0 = 2 * (lane & 3);
        #pragma unroll
        for (int mt = 0; mt < 2; ++mt)
        #pragma unroll
        for (int rp = 0; rp < 2; ++rp) {
            int row = m0 + mt * 16 + grp + rp * 8;
            int sl = row >> 5, bb = row & 31;
            if (s0 + sl < T_) {
                #pragma unroll
                for (int j = 0; j < 2; ++j) {
                    int n0 = nh * 16 + j * 8 + c0;
                    float y0 = 1.f / (1.f + __expf(-5.f * (acc[mt * 2 + j][rp * 2 + 0] + sB3[n0])));
                    float y1 = 1.f / (1.f + __expf(-5.f * (acc[mt * 2 + j][rp * 2 + 1] + sB3[n0 + 1])));
                    atomicMax(&sRed[bb * O_ + n0], __float_as_int(y0));
                    atomicMax(&sRed[bb * O_ + n0 + 1], __float_as_int(y1));
                }
            }
        }
    }
    __syncthreads();
    for (int i = tid; i < BB_ * O_; i += 256) {
        int bb = i >> 6, o = i & 63;
        atomicMax((int*)(out + (bb * T_ + t) * O_ + o), sRed[i]);
    }
}

// ---------------- launch ----------------
extern "C" void kernel_launch(void* const* d_in, const int* in_sizes, int n_in,
                              void* d_out, int out_size) {
    const float* P  = (const float*)d_in[0];
    const float* W1 = (const float*)d_in[1];
    const float* b1 = (const float*)d_in[2];
    const float* W2 = (const float*)d_in[3];
    const float* b2 = (const float*)d_in[4];
    const float* W3 = (const float*)d_in[5];
    const float* b3 = (const float*)d_in[6];
    float* out = (float*)d_out;

    cudaFuncSetAttribute(mlp_main_kernel, cudaFuncAttributeMaxDynamicSharedMemorySize, SMEM_TOTAL);

    prep_weights<<<(16 * 160 * NSTRIDE + 255) / 256, 256>>>(W1, W2, W3);
    compute_pre_kernel<<<(T_ * BB_ * D_) / 256, 256>>>(P);
    init_out_kernel<<<(BB_ * T_ * O_ + 255) / 256, 256>>>(out);
    mlp_main_kernel<<<dim3(64, T_), 256, SMEM_TOTAL>>>(P, b1, b2, b3, out);
}

// round 5
// speedup vs baseline: 2.2935x; 1.1670x over previous
#include <cuda_runtime.h>
#include <cuda_bf16.h>
#include <math.h>
#include <stdint.h>

#define BB_ 32
#define T_ 128
#define D_ 128
#define H_ 132
#define O_ 64

#define NSTRIDE 40                    // bf16 per n-row (80B): [16k hi][16k lo][8B pad] -> ldmatrix conflict-free
#define WBUF (160 * 80)               // 12800 B, one k-step chunk (N=160 padded)
#define WCH_C (64 * 80)               // 5120 B, stage-C chunk

// ---------------- SMEM layout ----------------
#define OFF_XH  0                     // 16 ksteps x 64 rows x 32B = 32768
#define OFF_XL  32768
#define OFF_W   65536                 // 2 x WBUF = 25600
#define OFF_B1  91136                 // 160 floats
#define OFF_B2  91776
#define OFF_B3  92416                 // 64 floats
#define OFF_RED 92672                 // 2048 ints
#define SMEM_TOTAL 100864

// ---------------- device scratch ----------------
__device__ float g_pre2[T_ * 64 * BB_ * D_];         // [t][c][bb][d] prefix max over [t, t+2(c+1))
__device__ __nv_bfloat16 g_W1s[16 * 160 * NSTRIDE];  // [kstep][n][40]
__device__ __nv_bfloat16 g_W2s[9 * 160 * NSTRIDE];
__device__ __nv_bfloat16 g_W3s[9 * 64 * NSTRIDE];

// ---------------- asm helpers ----------------
__device__ __forceinline__ void mma_bf16(float d[4], const uint32_t a[4], const uint32_t b[2]) {
    asm volatile("mma.sync.aligned.m16n8k16.row.col.f32.bf16.bf16.f32 "
                 "{%0,%1,%2,%3}, {%4,%5,%6,%7}, {%8,%9}, {%0,%1,%2,%3};"
                 : "+f"(d[0]), "+f"(d[1]), "+f"(d[2]), "+f"(d[3])
                 : "r"(a[0]), "r"(a[1]), "r"(a[2]), "r"(a[3]), "r"(b[0]), "r"(b[1]));
}
__device__ __forceinline__ uint32_t smem_u32(const void* p) {
    uint32_t a;
    asm("{ .reg .u64 t; cvta.to.shared.u64 t, %1; cvt.u32.u64 %0, t; }" : "=r"(a) : "l"(p));
    return a;
}
#define CP16(dst, src) asm volatile("cp.async.ca.shared.global [%0], [%1], 16;" :: "r"(dst), "l"(src) : "memory")
#define CP_COMMIT()    asm volatile("cp.async.commit_group;" ::: "memory")
#define CP_WAIT0()     asm volatile("cp.async.wait_group 0;" ::: "memory")
#define LDSM4(r, a) asm volatile("ldmatrix.sync.aligned.m8n8.x4.shared.b16 {%0,%1,%2,%3}, [%4];" \
    : "=r"((r)[0]), "=r"((r)[1]), "=r"((r)[2]), "=r"((r)[3]) : "r"(a))
#define LDSM2(r, a) asm volatile("ldmatrix.sync.aligned.m8n8.x2.shared.b16 {%0,%1}, [%2];" \
    : "=r"((r)[0]), "=r"((r)[1]) : "r"(a))

// X element address with 16B-half swizzle (kills A-frag/ldmatrix bank conflicts)
__device__ __forceinline__ int x_off(int ks, int row, int kk) {
    int phys = (kk >> 3) ^ ((row >> 2) & 1);
    return ks * 2048 + row * 32 + phys * 16 + (kk & 7) * 2;
}

// ---------------- prep: hi/lo split weights, N padded to 160, n-stride 80B ----------------
__global__ void prep_weights(const float* __restrict__ W1, const float* __restrict__ W2,
                             const float* __restrict__ W3) {
    int i = blockIdx.x * blockDim.x + threadIdx.x;
    if (i < 16 * 160 * NSTRIDE) {
        int ks = i / (160 * NSTRIDE), r = i % (160 * NSTRIDE);
        int n = r / NSTRIDE, q = r % NSTRIDE;
        int half = q >> 4, kk = q & 15;
        __nv_bfloat16 o = __float2bfloat16(0.f);
        if (half < 2 && n < H_) {
            float w = W1[(ks * 16 + kk) * H_ + n];
            __nv_bfloat16 hi = __float2bfloat16(w);
            o = half ? __float2bfloat16(w - __bfloat162float(hi)) : hi;
        }
        g_W1s[i] = o;
    }
    if (i < 9 * 160 * NSTRIDE) {
        int ks = i / (160 * NSTRIDE), r = i % (160 * NSTRIDE);
        int n = r / NSTRIDE, q = r % NSTRIDE;
        int half = q >> 4, kk = q & 15;
        int k = ks * 16 + kk;
        __nv_bfloat16 o = __float2bfloat16(0.f);
        if (half < 2 && n < H_ && k < H_) {
            float w = W2[k * H_ + n];
            __nv_bfloat16 hi = __float2bfloat16(w);
            o = half ? __float2bfloat16(w - __bfloat162float(hi)) : hi;
        }
        g_W2s[i] = o;
    }
    if (i < 9 * 64 * NSTRIDE) {
        int ks = i / (64 * NSTRIDE), r = i % (64 * NSTRIDE);
        int n = r / NSTRIDE, q = r % NSTRIDE;
        int half = q >> 4, kk = q & 15;
        int k = ks * 16 + kk;
        __nv_bfloat16 o = __float2bfloat16(0.f);
        if (half < 2 && k < H_) {
            float w = W3[k * O_ + n];
            __nv_bfloat16 hi = __float2bfloat16(w);
            o = half ? __float2bfloat16(w - __bfloat162float(hi)) : hi;
        }
        g_W3s[i] = o;
    }
}

// ---------------- prefix max at 2-step boundaries ----------------
__global__ void compute_pre_kernel(const float* __restrict__ P) {
    int idx = blockIdx.x * blockDim.x + threadIdx.x;
    int t = idx >> 12, bb = (idx >> 7) & 31, d = idx & 127;
    const float* Pp = P + bb * (T_ * D_) + d;
    float run = -3.4e38f;
    for (int s = t; s < T_; ++s) {
        run = fmaxf(run, Pp[s * D_]);
        int m = s - t + 1;
        if ((m & 1) == 0) {
            int ci = (m >> 1) - 1;
            if (ci < 64) g_pre2[((t * 64 + ci) * BB_ + bb) * D_ + d] = run;
        }
    }
}

__global__ void init_out_kernel(float* out) {
    int i = blockIdx.x * blockDim.x + threadIdx.x;
    if (i < BB_ * T_ * O_) out[i] = 0.f;
}

// ---------------- GEMM stage: cp.async depth-1 stream, ldmatrix frags, pass-ordered MMAs ----------------
template <int K16, int NT>
__device__ __forceinline__ void gemm_stage(const char* __restrict__ Wg, int chunk_bytes,
                                           uint32_t su, float (*acc)[4],
                                           const uint32_t aH[2], const uint32_t aL[2],
                                           const uint32_t* bOff, int tid) {
    for (int off = tid * 16; off < chunk_bytes; off += 4096)
        CP16(su + OFF_W + off, Wg + off);
    CP_COMMIT();
    #pragma unroll 1
    for (int k = 0; k < K16; ++k) {
        CP_WAIT0();
        __syncthreads();
        if (k + 1 < K16) {
            const char* src = Wg + (size_t)(k + 1) * chunk_bytes;
            uint32_t dst = su + OFF_W + ((k + 1) & 1) * WBUF;
            for (int off = tid * 16; off < chunk_bytes; off += 4096)
                CP16(dst + off, src + off);
        }
        CP_COMMIT();
        uint32_t wb = su + OFF_W + (k & 1) * WBUF;
        uint32_t ah[2][4], al[2][4];
        LDSM4(ah[0], aH[0] + k * 2048);
        LDSM4(ah[1], aH[1] + k * 2048);
        LDSM4(al[0], aL[0] + k * 2048);
        LDSM4(al[1], aL[1] + k * 2048);
        uint32_t bh[2 * NT], bl[2 * NT];
        if (NT == 5) {
            LDSM4(bh, wb + bOff[0]);      LDSM4(bh + 4, wb + bOff[1]);      LDSM2(bh + 8, wb + bOff[2]);
            LDSM4(bl, wb + bOff[0] + 32); LDSM4(bl + 4, wb + bOff[1] + 32); LDSM2(bl + 8, wb + bOff[2] + 32);
        } else {
            LDSM4(bh, wb + bOff[0]);
            LDSM4(bl, wb + bOff[0] + 32);
        }
        // pass-ordered: accumulator reuse distance = 2*NT
        #pragma unroll
        for (int j = 0; j < NT; ++j) { mma_bf16(acc[j], ah[0], bh + 2 * j); mma_bf16(acc[NT + j], ah[1], bh + 2 * j); }
        #pragma unroll
        for (int j = 0; j < NT; ++j) { mma_bf16(acc[j], al[0], bh + 2 * j); mma_bf16(acc[NT + j], al[1], bh + 2 * j); }
        #pragma unroll
        for (int j = 0; j < NT; ++j) { mma_bf16(acc[j], ah[0], bl + 2 * j); mma_bf16(acc[NT + j], ah[1], bl + 2 * j); }
    }
}

// ---------------- relu epilogue: write hi/lo X tiles for next stage ----------------
__device__ __forceinline__ void epi_relu(char* smem, float (*acc)[4], const float* bias,
                                         int m0, int nbase, int lane) {
    char* xh = smem + OFF_XH;
    char* xl = smem + OFF_XL;
    const int grp = lane >> 2;
    const int c0 = 2 * (lane & 3);
    #pragma unroll
    for (int mt = 0; mt < 2; ++mt)
    #pragma unroll
    for (int j = 0; j < 5; ++j) {
        int n0 = nbase + j * 8 + c0;
        if (n0 >= 144) continue;
        float bv0 = bias[n0], bv1 = bias[n0 + 1];
        int ks = n0 >> 4, kk = n0 & 15;
        #pragma unroll
        for (int rp = 0; rp < 2; ++rp) {
            int row = m0 + mt * 16 + grp + rp * 8;
            float v0 = fmaxf(acc[mt * 5 + j][rp * 2 + 0] + bv0, 0.f);
            float v1 = fmaxf(acc[mt * 5 + j][rp * 2 + 1] + bv1, 0.f);
            __nv_bfloat16 h0 = __float2bfloat16(v0), h1 = __float2bfloat16(v1);
            __nv_bfloat162 hp; hp.x = h0; hp.y = h1;
            __nv_bfloat162 lp;
            lp.x = __float2bfloat16(v0 - __bfloat162float(h0));
            lp.y = __float2bfloat16(v1 - __bfloat162float(h1));
            int off = x_off(ks, row, kk);
            *(__nv_bfloat162*)(xh + off) = hp;
            *(__nv_bfloat162*)(xl + off) = lp;
        }
    }
}

// ---------------- main ----------------
__global__ void __launch_bounds__(256, 2)
mlp_main_kernel(const float* __restrict__ P,
                const float* __restrict__ b1, const float* __restrict__ b2,
                const float* __restrict__ b3, float* __restrict__ out) {
    const int t = blockIdx.y;
    const int c = blockIdx.x;
    const int nch = (T_ - t + 1) >> 1;
    if (c >= nch) return;
    const int s0 = t + 2 * c;

    extern __shared__ char smem[];
    uint32_t su = smem_u32(smem);
    const int tid = threadIdx.x;
    float* sB1 = (float*)(smem + OFF_B1);
    float* sB2 = (float*)(smem + OFF_B2);
    float* sB3 = (float*)(smem + OFF_B3);
    int* sRed = (int*)(smem + OFF_RED);

    for (int i = tid; i < 160; i += 256) {
        sB1[i] = (i < H_) ? b1[i] : 0.f;
        sB2[i] = (i < H_) ? b2[i] : 0.f;
    }
    if (tid < 64) sB3[tid] = b3[tid];
    for (int i = tid; i < BB_ * O_; i += 256) sRed[i] = 0;

    // feature build: rows r = sl*32+bb (sl in 0..1); K cols [0,128)=running max, [128,256)=P
    {
        int d = tid & 127, half = tid >> 7;
        char* xh = smem + OFF_XH;
        char* xl = smem + OFF_XL;
        int ksM = d >> 4, kk = d & 15;
        for (int bb = half * 16; bb < half * 16 + 16; ++bb) {
            float run = (c > 0) ? g_pre2[((t * 64 + (c - 1)) * BB_ + bb) * D_ + d] : -3.4e38f;
            #pragma unroll
            for (int sl = 0; sl < 2; ++sl) {
                int s = s0 + sl;
                float pv = 0.f;
                if (s < T_) { pv = P[(bb * T_ + s) * D_ + d]; run = fmaxf(run, pv); }
                int row = sl * 32 + bb;
                int offM = x_off(ksM, row, kk);
                int offP = x_off(8 + ksM, row, kk);
                __nv_bfloat16 hm = __float2bfloat16(run);
                *(__nv_bfloat16*)(xh + offM) = hm;
                *(__nv_bfloat16*)(xl + offM) = __float2bfloat16(run - __bfloat162float(hm));
                __nv_bfloat16 hq = __float2bfloat16(pv);
                *(__nv_bfloat16*)(xh + offP) = hq;
                *(__nv_bfloat16*)(xl + offP) = __float2bfloat16(pv - __bfloat162float(hq));
            }
        }
    }
    __syncthreads();

    const int wid = tid >> 5, lane = tid & 31;
    const int m0 = (wid & 1) * 32;
    const int nh = wid >> 1;

    // per-lane ldmatrix addresses (hoisted out of all k-loops)
    uint32_t aH[2], aL[2], bAB[3], bC[1];
    {
        int l15 = lane & 15, chnk = lane >> 4;
        #pragma unroll
        for (int mt = 0; mt < 2; ++mt) {
            int row = m0 + mt * 16 + l15;
            int phys = chnk ^ ((row >> 2) & 1);
            aH[mt] = su + OFF_XH + row * 32 + phys * 16;
            aL[mt] = aH[mt] + (OFF_XL - OFF_XH);
        }
        int mrow = lane & 7;
        int halfk = (lane >> 3) & 1;
        int pair = lane >> 4;
        int nbA = nh * 40;
        bAB[0] = (uint32_t)((nbA + pair * 8 + mrow) * 80 + halfk * 16);
        bAB[1] = (uint32_t)((nbA + 16 + pair * 8 + mrow) * 80 + halfk * 16);
        bAB[2] = (uint32_t)((nbA + 32 + mrow) * 80 + halfk * 16);
        bC[0]  = (uint32_t)((nh * 16 + pair * 8 + mrow) * 80 + halfk * 16);
    }

    float acc[10][4];

    // Stage A: K=256 (16 ksteps), N=160 padded
    #pragma unroll
    for (int i = 0; i < 10; ++i) { acc[i][0] = acc[i][1] = acc[i][2] = acc[i][3] = 0.f; }
    gemm_stage<16, 5>((const char*)g_W1s, WBUF, su, acc, aH, aL, bAB, tid);
    __syncthreads();
    epi_relu(smem, acc, sB1, m0, nh * 40, lane);
    __syncthreads();

    // Stage B: K=144 (9 ksteps), N=160 padded
    #pragma unroll
    for (int i = 0; i < 10; ++i) { acc[i][0] = acc[i][1] = acc[i][2] = acc[i][3] = 0.f; }
    gemm_stage<9, 5>((const char*)g_W2s, WBUF, su, acc, aH, aL, bAB, tid);
    __syncthreads();
    epi_relu(smem, acc, sB2, m0, nh * 40, lane);
    __syncthreads();

    // Stage C: K=144 (9 ksteps), N=64
    #pragma unroll
    for (int i = 0; i < 4; ++i) { acc[i][0] = acc[i][1] = acc[i][2] = acc[i][3] = 0.f; }
    gemm_stage<9, 2>((const char*)g_W3s, WCH_C, su, acc, aH, aL, bC, tid);

    // final epilogue: sigmoid + max reduce
    {
        const int grp = lane >> 2;
        const int c0 = 2 * (lane & 3);
        #pragma unroll
        for (int mt = 0; mt < 2; ++mt)
        #pragma unroll
        for (int rp = 0; rp < 2; ++rp) {
            int row = m0 + mt * 16 + grp + rp * 8;
            int sl = row >> 5, bb = row & 31;
            if (s0 + sl < T_) {
                #pragma unroll
                for (int j = 0; j < 2; ++j) {
                    int n0 = nh * 16 + j * 8 + c0;
                    float y0 = 1.f / (1.f + __expf(-5.f * (acc[mt * 2 + j][rp * 2 + 0] + sB3[n0])));
                    float y1 = 1.f / (1.f + __expf(-5.f * (acc[mt * 2 + j][rp * 2 + 1] + sB3[n0 + 1])));
                    atomicMax(&sRed[bb * O_ + n0], __float_as_int(y0));
                    atomicMax(&sRed[bb * O_ + n0 + 1], __float_as_int(y1));
                }
            }
        }
    }
    __syncthreads();
    for (int i = tid; i < BB_ * O_; i += 256) {
        int bb = i >> 6, o = i & 63;
        atomicMax((int*)(out + (bb * T_ + t) * O_ + o), sRed[i]);
    }
}

// ---------------- launch ----------------
extern "C" void kernel_launch(void* const* d_in, const int* in_sizes, int n_in,
                              void* d_out, int out_size) {
    const float* P  = (const float*)d_in[0];
    const float* W1 = (const float*)d_in[1];
    const float* b1 = (const float*)d_in[2];
    const float* W2 = (const float*)d_in[3];
    const float* b2 = (const float*)d_in[4];
    const float* W3 = (const float*)d_in[5];
    const float* b3 = (const float*)d_in[6];
    float* out = (float*)d_out;

    cudaFuncSetAttribute(mlp_main_kernel, cudaFuncAttributeMaxDynamicSharedMemorySize, SMEM_TOTAL);

    prep_weights<<<(16 * 160 * NSTRIDE + 255) / 256, 256>>>(W1, W2, W3);
    compute_pre_kernel<<<(T_ * BB_ * D_) / 256, 256>>>(P);
    init_out_kernel<<<(BB_ * T_ * O_ + 255) / 256, 256>>>(out);
    mlp_main_kernel<<<dim3(64, T_), 256, SMEM_TOTAL>>>(P, b1, b2, b3, out);
}

// round 6
// speedup vs baseline: 2.5792x; 1.1245x over previous
#include <cuda_runtime.h>
#include <cuda_bf16.h>
#include <math.h>
#include <stdint.h>

#define BB_ 32
#define T_ 128
#define D_ 128
#define H_ 132
#define O_ 64

#define NSTRIDE 40                    // bf16 per n-row (80B): [16k hi][16k lo][8B pad]
#define WBUF (144 * 80)               // 11520 B per k-step chunk (N=144)
#define WCH_C (64 * 80)               // 5120 B stage-C chunk

// ---------------- SMEM layout ----------------
#define OFF_XH  0                     // 9 ksteps x 64 rows x 32B = 18432
#define OFF_XL  18432
#define OFF_W   36864                 // 2 x WBUF = 23040
#define OFF_B2  59904                 // 144 floats
#define OFF_B3  60480                 // 64 floats
#define OFF_RED 60736                 // 2048 ints
#define SMEM_TOTAL 68928

// ---------------- device scratch ----------------
__device__ float g_pre2[T_ * 64 * BB_ * D_];        // [t][c][bb][d] prefix max over [t, t+2(c+1))
__device__ float g_PW[T_ * BB_ * 144];              // [s][bb][n]: P(s,bb)·W1[128:256] + b1
__device__ __nv_bfloat16 g_W1s[8 * 144 * NSTRIDE];  // [kstep][n][40], W1 rows 0..127 (M part)
__device__ __nv_bfloat16 g_W2s[9 * 144 * NSTRIDE];
__device__ __nv_bfloat16 g_W3s[9 * 64 * NSTRIDE];

// ---------------- asm helpers ----------------
__device__ __forceinline__ void mma_bf16(float d[4], const uint32_t a[4], const uint32_t b[2]) {
    asm volatile("mma.sync.aligned.m16n8k16.row.col.f32.bf16.bf16.f32 "
                 "{%0,%1,%2,%3}, {%4,%5,%6,%7}, {%8,%9}, {%0,%1,%2,%3};"
                 : "+f"(d[0]), "+f"(d[1]), "+f"(d[2]), "+f"(d[3])
                 : "r"(a[0]), "r"(a[1]), "r"(a[2]), "r"(a[3]), "r"(b[0]), "r"(b[1]));
}
__device__ __forceinline__ uint32_t smem_u32(const void* p) {
    uint32_t a;
    asm("{ .reg .u64 t; cvta.to.shared.u64 t, %1; cvt.u32.u64 %0, t; }" : "=r"(a) : "l"(p));
    return a;
}
#define CP16(dst, src) asm volatile("cp.async.ca.shared.global [%0], [%1], 16;" :: "r"(dst), "l"(src) : "memory")
#define CP_COMMIT()    asm volatile("cp.async.commit_group;" ::: "memory")
#define CP_WAIT0()     asm volatile("cp.async.wait_group 0;" ::: "memory")
#define LDSM4(r, a) asm volatile("ldmatrix.sync.aligned.m8n8.x4.shared.b16 {%0,%1,%2,%3}, [%4];" \
    : "=r"((r)[0]), "=r"((r)[1]), "=r"((r)[2]), "=r"((r)[3]) : "r"(a))
#define LDSM2(r, a) asm volatile("ldmatrix.sync.aligned.m8n8.x2.shared.b16 {%0,%1}, [%2];" \
    : "=r"((r)[0]), "=r"((r)[1]) : "r"(a))

// X element address with 16B-half swizzle (ldmatrix conflict-free)
__device__ __forceinline__ int x_off(int ks, int row, int kk) {
    int phys = (kk >> 3) ^ ((row >> 2) & 1);
    return ks * 2048 + row * 32 + phys * 16 + (kk & 7) * 2;
}

// ---------------- prep: hi/lo split weights, N padded to 144 ----------------
__global__ void prep_weights(const float* __restrict__ W1, const float* __restrict__ W2,
                             const float* __restrict__ W3) {
    int i = blockIdx.x * blockDim.x + threadIdx.x;
    if (i < 8 * 144 * NSTRIDE) {
        int ks = i / (144 * NSTRIDE), r = i % (144 * NSTRIDE);
        int n = r / NSTRIDE, q = r % NSTRIDE;
        int half = q >> 4, kk = q & 15;
        __nv_bfloat16 o = __float2bfloat16(0.f);
        if (half < 2 && n < H_) {
            float w = W1[(ks * 16 + kk) * H_ + n];
            __nv_bfloat16 hi = __float2bfloat16(w);
            o = half ? __float2bfloat16(w - __bfloat162float(hi)) : hi;
        }
        g_W1s[i] = o;
    }
    if (i < 9 * 144 * NSTRIDE) {
        int ks = i / (144 * NSTRIDE), r = i % (144 * NSTRIDE);
        int n = r / NSTRIDE, q = r % NSTRIDE;
        int half = q >> 4, kk = q & 15;
        int k = ks * 16 + kk;
        __nv_bfloat16 o = __float2bfloat16(0.f);
        if (half < 2 && n < H_ && k < H_) {
            float w = W2[k * H_ + n];
            __nv_bfloat16 hi = __float2bfloat16(w);
            o = half ? __float2bfloat16(w - __bfloat162float(hi)) : hi;
        }
        g_W2s[i] = o;
    }
    if (i < 9 * 64 * NSTRIDE) {
        int ks = i / (64 * NSTRIDE), r = i % (64 * NSTRIDE);
        int n = r / NSTRIDE, q = r % NSTRIDE;
        int half = q >> 4, kk = q & 15;
        int k = ks * 16 + kk;
        __nv_bfloat16 o = __float2bfloat16(0.f);
        if (half < 2 && k < H_) {
            float w = W3[k * O_ + n];
            __nv_bfloat16 hi = __float2bfloat16(w);
            o = half ? __float2bfloat16(w - __bfloat162float(hi)) : hi;
        }
        g_W3s[i] = o;
    }
}

// ---------------- prefix max at 2-step boundaries ----------------
__global__ void compute_pre_kernel(const float* __restrict__ P) {
    int idx = blockIdx.x * blockDim.x + threadIdx.x;
    int t = idx >> 12, bb = (idx >> 7) & 31, d = idx & 127;
    const float* Pp = P + bb * (T_ * D_) + d;
    float run = -3.4e38f;
    for (int s = t; s < T_; ++s) {
        run = fmaxf(run, Pp[s * D_]);
        int m = s - t + 1;
        if ((m & 1) == 0) {
            int ci = (m >> 1) - 1;
            if (ci < 64) g_pre2[((t * 64 + ci) * BB_ + bb) * D_ + d] = run;
        }
    }
}

// ---------------- PW[s][bb][n] = P(bb,s,:)·W1[128:256, n] + b1[n], exact fp32 ----------------
#define PW_SMEM (16384 + 73728)
__global__ void compute_pw_kernel(const float* __restrict__ P, const float* __restrict__ W1,
                                  const float* __restrict__ b1) {
    extern __shared__ char sm[];
    float* sP = (float*)sm;               // [32][128]
    float* sW = (float*)(sm + 16384);     // [128][144]
    int s = blockIdx.x;
    int tid = threadIdx.x;
    for (int i = tid; i < BB_ * D_; i += 256) {
        int bb = i >> 7, d = i & 127;
        sP[i] = P[(bb * T_ + s) * D_ + d];
    }
    for (int i = tid; i < 128 * 144; i += 256) {
        int d = i / 144, n = i % 144;
        sW[i] = (n < H_) ? W1[(128 + d) * H_ + n] : 0.f;
    }
    __syncthreads();
    for (int i = tid; i < BB_ * 72; i += 256) {
        int bb = i / 72, n = (i % 72) * 2;
        float ax = (n < H_) ? b1[n] : 0.f;
        float ay = (n + 1 < H_) ? b1[n + 1] : 0.f;
        const float* pr = sP + bb * 128;
        #pragma unroll 8
        for (int d = 0; d < 128; ++d) {
            float p = pr[d];
            ax += p * sW[d * 144 + n];
            ay += p * sW[d * 144 + n + 1];
        }
        float2 v; v.x = ax; v.y = ay;
        *(float2*)(g_PW + (s * BB_ + bb) * 144 + n) = v;
    }
}

__global__ void init_out_kernel(float* out) {
    int i = blockIdx.x * blockDim.x + threadIdx.x;
    if (i < BB_ * T_ * O_) out[i] = 0.f;
}

// ---------------- GEMM stage: cp.async stream, ldmatrix frags, pass-ordered MMAs ----------------
template <int K16, int NT>
__device__ __forceinline__ void gemm_stage(const char* __restrict__ Wg, int chunk_bytes,
                                           uint32_t su, float (*acc)[4],
                                           uint32_t aH, uint32_t aL,
                                           const uint32_t* bOff, int tid) {
    for (int off = tid * 16; off < chunk_bytes; off += 4096)
        CP16(su + OFF_W + off, Wg + off);
    CP_COMMIT();
    #pragma unroll 1
    for (int k = 0; k < K16; ++k) {
        CP_WAIT0();
        __syncthreads();
        if (k + 1 < K16) {
            const char* src = Wg + (size_t)(k + 1) * chunk_bytes;
            uint32_t dst = su + OFF_W + ((k + 1) & 1) * WBUF;
            for (int off = tid * 16; off < chunk_bytes; off += 4096)
                CP16(dst + off, src + off);
        }
        CP_COMMIT();
        uint32_t wb = su + OFF_W + (k & 1) * WBUF;
        uint32_t ah[4], al[4];
        LDSM4(ah, aH + k * 2048);
        LDSM4(al, aL + k * 2048);
        uint32_t bh[2 * NT], bl[2 * NT];
        if (NT == 9) {
            LDSM4(bh, wb + bOff[0]); LDSM4(bh + 4, wb + bOff[1]);
            LDSM4(bh + 8, wb + bOff[2]); LDSM4(bh + 12, wb + bOff[3]);
            LDSM2(bh + 16, wb + bOff[4]);
        } else {
            LDSM4(bh, wb + bOff[0]); LDSM4(bh + 4, wb + bOff[1]);
        }
        // pass 1: hi·hi
        #pragma unroll
        for (int j = 0; j < NT; ++j) mma_bf16(acc[j], ah, bh + 2 * j);
        // load lo weights (latency hidden under pass 2)
        if (NT == 9) {
            LDSM4(bl, wb + bOff[0] + 32); LDSM4(bl + 4, wb + bOff[1] + 32);
            LDSM4(bl + 8, wb + bOff[2] + 32); LDSM4(bl + 12, wb + bOff[3] + 32);
            LDSM2(bl + 16, wb + bOff[4] + 32);
        } else {
            LDSM4(bl, wb + bOff[0] + 32); LDSM4(bl + 4, wb + bOff[1] + 32);
        }
        // pass 2: lo(X)·hi(W)
        #pragma unroll
        for (int j = 0; j < NT; ++j) mma_bf16(acc[j], al, bh + 2 * j);
        // pass 3: hi(X)·lo(W)
        #pragma unroll
        for (int j = 0; j < NT; ++j) mma_bf16(acc[j], ah, bl + 2 * j);
    }
}

// ---------------- relu epilogue: write hi/lo X tiles for next stage ----------------
__device__ __forceinline__ void epi_relu(char* smem, float (*acc)[4], const float* bias,
                                         int m0, int nbase, int lane) {
    char* xh = smem + OFF_XH;
    char* xl = smem + OFF_XL;
    const int grp = lane >> 2;
    const int c0 = 2 * (lane & 3);
    #pragma unroll
    for (int j = 0; j < 9; ++j) {
        int n0 = nbase + j * 8 + c0;
        float bv0 = bias ? bias[n0] : 0.f;
        float bv1 = bias ? bias[n0 + 1] : 0.f;
        int ks = n0 >> 4, kk = n0 & 15;
        #pragma unroll
        for (int rp = 0; rp < 2; ++rp) {
            int row = m0 + grp + rp * 8;
            float v0 = fmaxf(acc[j][rp * 2 + 0] + bv0, 0.f);
            float v1 = fmaxf(acc[j][rp * 2 + 1] + bv1, 0.f);
            __nv_bfloat16 h0 = __float2bfloat16(v0), h1 = __float2bfloat16(v1);
            __nv_bfloat162 hp; hp.x = h0; hp.y = h1;
            __nv_bfloat162 lp;
            lp.x = __float2bfloat16(v0 - __bfloat162float(h0));
            lp.y = __float2bfloat16(v1 - __bfloat162float(h1));
            int off = x_off(ks, row, kk);
            *(__nv_bfloat162*)(xh + off) = hp;
            *(__nv_bfloat162*)(xl + off) = lp;
        }
    }
}

// ---------------- main ----------------
__global__ void __launch_bounds__(256, 2)
mlp_main_kernel(const float* __restrict__ P,
                const float* __restrict__ b2, const float* __restrict__ b3,
                float* __restrict__ out) {
    const int t = blockIdx.y;
    const int c = blockIdx.x;
    const int nch = (T_ - t + 1) >> 1;
    if (c >= nch) return;
    const int s0 = t + 2 * c;

    extern __shared__ char smem[];
    uint32_t su = smem_u32(smem);
    const int tid = threadIdx.x;
    float* sB2 = (float*)(smem + OFF_B2);
    float* sB3 = (float*)(smem + OFF_B3);
    int* sRed = (int*)(smem + OFF_RED);

    for (int i = tid; i < 144; i += 256) sB2[i] = (i < H_) ? b2[i] : 0.f;
    if (tid < 64) sB3[tid] = b3[tid];
    for (int i = tid; i < BB_ * O_; i += 256) sRed[i] = 0;

    // feature build: rows r = sl*32+bb (sl 0..1); K cols [0,128) = running max only
    {
        int d = tid & 127, half = tid >> 7;
        char* xh = smem + OFF_XH;
        char* xl = smem + OFF_XL;
        int ksM = d >> 4, kk = d & 15;
        for (int bb = half * 16; bb < half * 16 + 16; ++bb) {
            float run = (c > 0) ? g_pre2[((t * 64 + (c - 1)) * BB_ + bb) * D_ + d] : -3.4e38f;
            #pragma unroll
            for (int sl = 0; sl < 2; ++sl) {
                int s = s0 + sl;
                if (s < T_) run = fmaxf(run, P[(bb * T_ + s) * D_ + d]);
                int row = sl * 32 + bb;
                int offM = x_off(ksM, row, kk);
                __nv_bfloat16 hm = __float2bfloat16(run);
                *(__nv_bfloat16*)(xh + offM) = hm;
                *(__nv_bfloat16*)(xl + offM) = __float2bfloat16(run - __bfloat162float(hm));
            }
        }
    }
    __syncthreads();

    const int wid = tid >> 5, lane = tid & 31;
    const int mq = wid & 3, nq = wid >> 2;      // 4 m-tiles x 2 n-halves
    const int m0 = mq * 16;
    const int grp = lane >> 2, c0 = 2 * (lane & 3);

    // per-lane ldmatrix addresses
    uint32_t aH, aL, bAB[5], bC[2];
    {
        int l15 = lane & 15, chnk = lane >> 4;
        int row = m0 + l15;
        int phys = chnk ^ ((row >> 2) & 1);
        aH = su + OFF_XH + row * 32 + phys * 16;
        aL = aH + (OFF_XL - OFF_XH);
        int l7 = lane & 7, kh = (lane >> 3) & 1, pr = (lane >> 4) & 1;
        #pragma unroll
        for (int i = 0; i < 4; ++i)
            bAB[i] = (uint32_t)((nq * 72 + 16 * i + pr * 8 + l7) * 80 + kh * 16);
        bAB[4] = (uint32_t)((nq * 72 + 64 + l7) * 80 + kh * 16);
        #pragma unroll
        for (int i = 0; i < 2; ++i)
            bC[i] = (uint32_t)((nq * 32 + 16 * i + pr * 8 + l7) * 80 + kh * 16);
    }

    float acc[9][4];

    // Stage A: acc preloaded from PW (P-part + b1, exact fp32), K=128 M-part only
    {
        int row_lo = m0 + grp, row_hi = row_lo + 8;
        int sl_lo = row_lo >> 5, sl_hi = row_hi >> 5;
        int s_lo = min(s0 + sl_lo, T_ - 1), s_hi = min(s0 + sl_hi, T_ - 1);
        const float* pwlo = g_PW + (s_lo * BB_ + (row_lo & 31)) * 144;
        const float* pwhi = g_PW + (s_hi * BB_ + (row_hi & 31)) * 144;
        #pragma unroll
        for (int j = 0; j < 9; ++j) {
            int n0 = nq * 72 + j * 8 + c0;
            float2 vlo = *(const float2*)(pwlo + n0);
            float2 vhi = *(const float2*)(pwhi + n0);
            acc[j][0] = vlo.x; acc[j][1] = vlo.y;
            acc[j][2] = vhi.x; acc[j][3] = vhi.y;
        }
    }
    gemm_stage<8, 9>((const char*)g_W1s, WBUF, su, acc, aH, aL, bAB, tid);
    __syncthreads();
    epi_relu(smem, acc, (const float*)0, m0, nq * 72, lane);
    __syncthreads();

    // Stage B: K=144 (9 ksteps), N=144
    #pragma unroll
    for (int i = 0; i < 9; ++i) { acc[i][0] = acc[i][1] = acc[i][2] = acc[i][3] = 0.f; }
    gemm_stage<9, 9>((const char*)g_W2s, WBUF, su, acc, aH, aL, bAB, tid);
    __syncthreads();
    epi_relu(smem, acc, sB2, m0, nq * 72, lane);
    __syncthreads();

    // Stage C: K=144 (9 ksteps), N=64
    #pragma unroll
    for (int i = 0; i < 4; ++i) { acc[i][0] = acc[i][1] = acc[i][2] = acc[i][3] = 0.f; }
    gemm_stage<9, 4>((const char*)g_W3s, WCH_C, su, acc, aH, aL, bC, tid);

    // final epilogue: sigmoid + max reduce
    {
        #pragma unroll
        for (int rp = 0; rp < 2; ++rp) {
            int row = m0 + grp + rp * 8;
            int sl = row >> 5, bb = row & 31;
            if (s0 + sl < T_) {
                #pragma unroll
                for (int j = 0; j < 4; ++j) {
                    int n0 = nq * 32 + j * 8 + c0;
                    float y0 = 1.f / (1.f + __expf(-5.f * (acc[j][rp * 2 + 0] + sB3[n0])));
                    float y1 = 1.f / (1.f + __expf(-5.f * (acc[j][rp * 2 + 1] + sB3[n0 + 1])));
                    atomicMax(&sRed[bb * O_ + n0], __float_as_int(y0));
                    atomicMax(&sRed[bb * O_ + n0 + 1], __float_as_int(y1));
                }
            }
        }
    }
    __syncthreads();
    for (int i = tid; i < BB_ * O_; i += 256) {
        int bb = i >> 6, o = i & 63;
        atomicMax((int*)(out + (bb * T_ + t) * O_ + o), sRed[i]);
    }
}

// ---------------- launch ----------------
extern "C" void kernel_launch(void* const* d_in, const int* in_sizes, int n_in,
                              void* d_out, int out_size) {
    const float* P  = (const float*)d_in[0];
    const float* W1 = (const float*)d_in[1];
    const float* b1 = (const float*)d_in[2];
    const float* W2 = (const float*)d_in[3];
    const float* b2 = (const float*)d_in[4];
    const float* W3 = (const float*)d_in[5];
    const float* b3 = (const float*)d_in[6];
    float* out = (float*)d_out;

    cudaFuncSetAttribute(mlp_main_kernel, cudaFuncAttributeMaxDynamicSharedMemorySize, SMEM_TOTAL);
    cudaFuncSetAttribute(compute_pw_kernel, cudaFuncAttributeMaxDynamicSharedMemorySize, PW_SMEM);

    prep_weights<<<(9 * 144 * NSTRIDE + 255) / 256, 256>>>(W1, W2, W3);
    compute_pre_kernel<<<(T_ * BB_ * D_) / 256, 256>>>(P);
    compute_pw_kernel<<<T_, 256, PW_SMEM>>>(P, W1, b1);
    init_out_kernel<<<(BB_ * T_ * O_ + 255) / 256, 256>>>(out);
    mlp_main_kernel<<<dim3(64, T_), 256, SMEM_TOTAL>>>(P, b2, b3, out);
}

// round 8
// speedup vs baseline: 3.3459x; 1.2973x over previous
#include <cuda_runtime.h>
#include <cuda_bf16.h>
#include <math.h>
#include <stdint.h>

#define BB_ 32
#define T_ 128
#define D_ 128
#define H_ 132
#define O_ 64

#define NSTRIDE 40                    // bf16 per n-row (80B): [16k hi][16k lo][8B pad]
#define WBUF (144 * 80)               // 11520 B per k-step chunk (N=144)
#define WCH_C (64 * 80)               // 5120 B stage-C chunk

// ---------------- SMEM layout ----------------
#define OFF_XH  0                     // 9 ksteps x 128 rows x 32B = 36864
#define OFF_XL  36864
#define OFF_W   73728                 // 3 x WBUF = 34560 -> 108288
#define OFF_B2  108288                // 144 floats -> 108864
#define OFF_B3  108864                // 64 floats -> 109120
#define OFF_RED OFF_XH                // sRed (8192B) ALIASES X tile; used only after stage C
#define SMEM_TOTAL 109120             // x2 blocks = 218240 < 228KB/SM

// ---------------- device scratch ----------------
__device__ float g_pre4[T_ * 32 * BB_ * D_];        // [t][c][bb][d] prefix max over [t, t+4(c+1))
__device__ float g_PW[T_ * BB_ * 144];              // [s][bb][n]: P(s,bb)·W1[128:256] + b1
__device__ __nv_bfloat16 g_W1s[8 * 144 * NSTRIDE];  // [kstep][n][40], W1 rows 0..127 (M part)
__device__ __nv_bfloat16 g_W2s[9 * 144 * NSTRIDE];
__device__ __nv_bfloat16 g_W3s[9 * 64 * NSTRIDE];

// ---------------- asm helpers ----------------
__device__ __forceinline__ void mma_bf16(float d[4], const uint32_t a[4], const uint32_t b[2]) {
    asm volatile("mma.sync.aligned.m16n8k16.row.col.f32.bf16.bf16.f32 "
                 "{%0,%1,%2,%3}, {%4,%5,%6,%7}, {%8,%9}, {%0,%1,%2,%3};"
                 : "+f"(d[0]), "+f"(d[1]), "+f"(d[2]), "+f"(d[3])
                 : "r"(a[0]), "r"(a[1]), "r"(a[2]), "r"(a[3]), "r"(b[0]), "r"(b[1]));
}
__device__ __forceinline__ uint32_t smem_u32(const void* p) {
    uint32_t a;
    asm("{ .reg .u64 t; cvta.to.shared.u64 t, %1; cvt.u32.u64 %0, t; }" : "=r"(a) : "l"(p));
    return a;
}
#define CP16(dst, src) asm volatile("cp.async.ca.shared.global [%0], [%1], 16;" :: "r"(dst), "l"(src) : "memory")
#define CP_COMMIT()    asm volatile("cp.async.commit_group;" ::: "memory")
#define CP_WAIT1()     asm volatile("cp.async.wait_group 1;" ::: "memory")
#define LDSM4(r, a) asm volatile("ldmatrix.sync.aligned.m8n8.x4.shared.b16 {%0,%1,%2,%3}, [%4];" \
    : "=r"((r)[0]), "=r"((r)[1]), "=r"((r)[2]), "=r"((r)[3]) : "r"(a))
#define LDSM2(r, a) asm volatile("ldmatrix.sync.aligned.m8n8.x2.shared.b16 {%0,%1}, [%2];" \
    : "=r"((r)[0]), "=r"((r)[1]) : "r"(a))

// X element address with 16B-half swizzle (ldmatrix conflict-free); 128 rows/kstep
__device__ __forceinline__ int x_off(int ks, int row, int kk) {
    int phys = (kk >> 3) ^ ((row >> 2) & 1);
    return ks * 4096 + row * 32 + phys * 16 + (kk & 7) * 2;
}

// ---------------- prep: hi/lo split weights, N padded to 144 ----------------
__global__ void prep_weights(const float* __restrict__ W1, const float* __restrict__ W2,
                             const float* __restrict__ W3) {
    int i = blockIdx.x * blockDim.x + threadIdx.x;
    if (i < 8 * 144 * NSTRIDE) {
        int ks = i / (144 * NSTRIDE), r = i % (144 * NSTRIDE);
        int n = r / NSTRIDE, q = r % NSTRIDE;
        int half = q >> 4, kk = q & 15;
        __nv_bfloat16 o = __float2bfloat16(0.f);
        if (half < 2 && n < H_) {
            float w = W1[(ks * 16 + kk) * H_ + n];
            __nv_bfloat16 hi = __float2bfloat16(w);
            o = half ? __float2bfloat16(w - __bfloat162float(hi)) : hi;
        }
        g_W1s[i] = o;
    }
    if (i < 9 * 144 * NSTRIDE) {
        int ks = i / (144 * NSTRIDE), r = i % (144 * NSTRIDE);
        int n = r / NSTRIDE, q = r % NSTRIDE;
        int half = q >> 4, kk = q & 15;
        int k = ks * 16 + kk;
        __nv_bfloat16 o = __float2bfloat16(0.f);
        if (half < 2 && n < H_ && k < H_) {
            float w = W2[k * H_ + n];
            __nv_bfloat16 hi = __float2bfloat16(w);
            o = half ? __float2bfloat16(w - __bfloat162float(hi)) : hi;
        }
        g_W2s[i] = o;
    }
    if (i < 9 * 64 * NSTRIDE) {
        int ks = i / (64 * NSTRIDE), r = i % (64 * NSTRIDE);
        int n = r / NSTRIDE, q = r % NSTRIDE;
        int half = q >> 4, kk = q & 15;
        int k = ks * 16 + kk;
        __nv_bfloat16 o = __float2bfloat16(0.f);
        if (half < 2 && k < H_) {
            float w = W3[k * O_ + n];
            __nv_bfloat16 hi = __float2bfloat16(w);
            o = half ? __float2bfloat16(w - __bfloat162float(hi)) : hi;
        }
        g_W3s[i] = o;
    }
}

// ---------------- prefix max at 4-step boundaries ----------------
__global__ void compute_pre_kernel(const float* __restrict__ P) {
    int idx = blockIdx.x * blockDim.x + threadIdx.x;
    int t = idx >> 12, bb = (idx >> 7) & 31, d = idx & 127;
    const float* Pp = P + bb * (T_ * D_) + d;
    float run = -3.4e38f;
    for (int s = t; s < T_; ++s) {
        run = fmaxf(run, Pp[s * D_]);
        int m = s - t + 1;
        if ((m & 3) == 0) {
            int ci = (m >> 2) - 1;
            if (ci < 32) g_pre4[((t * 32 + ci) * BB_ + bb) * D_ + d] = run;
        }
    }
}

// ---------------- PW[s][bb][n] = P(bb,s,:)·W1[128:256, n] + b1[n], exact fp32 ----------------
#define PW_SMEM (16384 + 73728)
__global__ void compute_pw_kernel(const float* __restrict__ P, const float* __restrict__ W1,
                                  const float* __restrict__ b1) {
    extern __shared__ char sm[];
    float* sP = (float*)sm;               // [32][128]
    float* sW = (float*)(sm + 16384);     // [128][144]
    int s = blockIdx.x;
    int tid = threadIdx.x;
    for (int i = tid; i < BB_ * D_; i += 256) {
        int bb = i >> 7, d = i & 127;
        sP[i] = P[(bb * T_ + s) * D_ + d];
    }
    for (int i = tid; i < 128 * 144; i += 256) {
        int d = i / 144, n = i % 144;
        sW[i] = (n < H_) ? W1[(128 + d) * H_ + n] : 0.f;
    }
    __syncthreads();
    for (int i = tid; i < BB_ * 72; i += 256) {
        int bb = i / 72, n = (i % 72) * 2;
        float ax = (n < H_) ? b1[n] : 0.f;
        float ay = (n + 1 < H_) ? b1[n + 1] : 0.f;
        const float* pr = sP + bb * 128;
        #pragma unroll 8
        for (int d = 0; d < 128; ++d) {
            float p = pr[d];
            ax += p * sW[d * 144 + n];
            ay += p * sW[d * 144 + n + 1];
        }
        float2 v; v.x = ax; v.y = ay;
        *(float2*)(g_PW + (s * BB_ + bb) * 144 + n) = v;
    }
}

__global__ void init_out_kernel(float* out) {
    int i = blockIdx.x * blockDim.x + threadIdx.x;
    if (i < BB_ * T_ * O_) out[i] = 0.f;
}

// ---------------- GEMM stage: 3-buffer cp.async (wait 1), ldmatrix frags, 2 m-tiles ----------------
template <int K16, int NT>
__device__ __forceinline__ void gemm_stage(const char* __restrict__ Wg, int chunk_bytes,
                                           uint32_t su, float (*acc)[4],
                                           const uint32_t aH[2], const uint32_t aL[2],
                                           const uint32_t* bOff, int tid) {
    for (int off = tid * 16; off < chunk_bytes; off += 4096)
        CP16(su + OFF_W + off, Wg + off);
    CP_COMMIT();
    for (int off = tid * 16; off < chunk_bytes; off += 4096)
        CP16(su + OFF_W + WBUF + off, Wg + chunk_bytes + off);
    CP_COMMIT();
    #pragma unroll 1
    for (int k = 0; k < K16; ++k) {
        CP_WAIT1();
        __syncthreads();
        if (k + 2 < K16) {
            const char* src = Wg + (size_t)(k + 2) * chunk_bytes;
            uint32_t dst = su + OFF_W + ((k + 2) % 3) * WBUF;
            for (int off = tid * 16; off < chunk_bytes; off += 4096)
                CP16(dst + off, src + off);
        }
        CP_COMMIT();
        uint32_t wb = su + OFF_W + (k % 3) * WBUF;
        uint32_t ah[2][4], al[2][4];
        LDSM4(ah[0], aH[0] + k * 4096);
        LDSM4(ah[1], aH[1] + k * 4096);
        LDSM4(al[0], aL[0] + k * 4096);
        LDSM4(al[1], aL[1] + k * 4096);
        uint32_t b[2 * NT];                 // reused for hi then lo (saves 2*NT regs)
        if (NT == 9) {
            LDSM4(b, wb + bOff[0]); LDSM4(b + 4, wb + bOff[1]);
            LDSM4(b + 8, wb + bOff[2]); LDSM4(b + 12, wb + bOff[3]);
            LDSM2(b + 16, wb + bOff[4]);
        } else {
            LDSM4(b, wb + bOff[0]); LDSM4(b + 4, wb + bOff[1]);
        }
        // pass 1: hi(X)·hi(W)
        #pragma unroll
        for (int j = 0; j < NT; ++j) { mma_bf16(acc[j], ah[0], b + 2 * j); mma_bf16(acc[NT + j], ah[1], b + 2 * j); }
        // pass 2: lo(X)·hi(W)
        #pragma unroll
        for (int j = 0; j < NT; ++j) { mma_bf16(acc[j], al[0], b + 2 * j); mma_bf16(acc[NT + j], al[1], b + 2 * j); }
        // reload lo weights into same regs
        if (NT == 9) {
            LDSM4(b, wb + bOff[0] + 32); LDSM4(b + 4, wb + bOff[1] + 32);
            LDSM4(b + 8, wb + bOff[2] + 32); LDSM4(b + 12, wb + bOff[3] + 32);
            LDSM2(b + 16, wb + bOff[4] + 32);
        } else {
            LDSM4(b, wb + bOff[0] + 32); LDSM4(b + 4, wb + bOff[1] + 32);
        }
        // pass 3: hi(X)·lo(W)
        #pragma unroll
        for (int j = 0; j < NT; ++j) { mma_bf16(acc[j], ah[0], b + 2 * j); mma_bf16(acc[NT + j], ah[1], b + 2 * j); }
    }
}

// ---------------- relu epilogue: write hi/lo X tiles for next stage ----------------
__device__ __forceinline__ void epi_relu(char* smem, float (*acc)[4], const float* bias,
                                         int m0, int nbase, int lane) {
    char* xh = smem + OFF_XH;
    char* xl = smem + OFF_XL;
    const int grp = lane >> 2;
    const int c0 = 2 * (lane & 3);
    #pragma unroll
    for (int mt = 0; mt < 2; ++mt)
    #pragma unroll
    for (int j = 0; j < 9; ++j) {
        int n0 = nbase + j * 8 + c0;
        float bv0 = bias ? bias[n0] : 0.f;
        float bv1 = bias ? bias[n0 + 1] : 0.f;
        int ks = n0 >> 4, kk = n0 & 15;
        #pragma unroll
        for (int rp = 0; rp < 2; ++rp) {
            int row = m0 + mt * 64 + grp + rp * 8;
            float v0 = fmaxf(acc[mt * 9 + j][rp * 2 + 0] + bv0, 0.f);
            float v1 = fmaxf(acc[mt * 9 + j][rp * 2 + 1] + bv1, 0.f);
            __nv_bfloat16 h0 = __float2bfloat16(v0), h1 = __float2bfloat16(v1);
            __nv_bfloat162 hp; hp.x = h0; hp.y = h1;
            __nv_bfloat162 lp;
            lp.x = __float2bfloat16(v0 - __bfloat162float(h0));
            lp.y = __float2bfloat16(v1 - __bfloat162float(h1));
            int off = x_off(ks, row, kk);
            *(__nv_bfloat162*)(xh + off) = hp;
            *(__nv_bfloat162*)(xl + off) = lp;
        }
    }
}

// ---------------- main ----------------
__global__ void __launch_bounds__(256, 2)
mlp_main_kernel(const float* __restrict__ P,
                const float* __restrict__ b2, const float* __restrict__ b3,
                float* __restrict__ out) {
    const int t = blockIdx.y;
    const int c = blockIdx.x;
    const int nch = (T_ - t + 3) >> 2;
    if (c >= nch) return;
    const int s0 = t + 4 * c;

    extern __shared__ char smem[];
    uint32_t su = smem_u32(smem);
    const int tid = threadIdx.x;
    float* sB2 = (float*)(smem + OFF_B2);
    float* sB3 = (float*)(smem + OFF_B3);
    int* sRed = (int*)(smem + OFF_RED);    // ALIASES X tile; valid only after stage C

    for (int i = tid; i < 144; i += 256) sB2[i] = (i < H_) ? b2[i] : 0.f;
    if (tid < 64) sB3[tid] = b3[tid];

    // feature build: rows r = sl*32+bb (sl 0..3); K cols [0,128) = running max only
    {
        int d = tid & 127, half = tid >> 7;
        char* xh = smem + OFF_XH;
        char* xl = smem + OFF_XL;
        int ksM = d >> 4, kk = d & 15;
        for (int bb = half * 16; bb < half * 16 + 16; ++bb) {
            float run = (c > 0) ? g_pre4[((t * 32 + (c - 1)) * BB_ + bb) * D_ + d] : -3.4e38f;
            #pragma unroll
            for (int sl = 0; sl < 4; ++sl) {
                int s = s0 + sl;
                if (s < T_) run = fmaxf(run, P[(bb * T_ + s) * D_ + d]);
                int row = sl * 32 + bb;
                int offM = x_off(ksM, row, kk);
                __nv_bfloat16 hm = __float2bfloat16(run);
                *(__nv_bfloat16*)(xh + offM) = hm;
                *(__nv_bfloat16*)(xl + offM) = __float2bfloat16(run - __bfloat162float(hm));
            }
        }
    }
    __syncthreads();

    const int wid = tid >> 5, lane = tid & 31;
    const int mq = wid >> 1, nq = wid & 1;      // 4 m-quads x 2 n-halves; m-tiles at m0, m0+64
    const int m0 = mq * 16;
    const int grp = lane >> 2, c0 = 2 * (lane & 3);

    // per-lane ldmatrix addresses
    uint32_t aH[2], aL[2], bAB[5], bC[2];
    {
        int l15 = lane & 15, chnk = lane >> 4;
        #pragma unroll
        for (int mt = 0; mt < 2; ++mt) {
            int row = m0 + mt * 64 + l15;
            int phys = chnk ^ ((row >> 2) & 1);
            aH[mt] = su + OFF_XH + row * 32 + phys * 16;
            aL[mt] = aH[mt] + (OFF_XL - OFF_XH);
        }
        int l7 = lane & 7, kh = (lane >> 3) & 1, pr = (lane >> 4) & 1;
        #pragma unroll
        for (int i = 0; i < 4; ++i)
            bAB[i] = (uint32_t)((nq * 72 + 16 * i + pr * 8 + l7) * 80 + kh * 16);
        bAB[4] = (uint32_t)((nq * 72 + 64 + l7) * 80 + kh * 16);
        #pragma unroll
        for (int i = 0; i < 2; ++i)
            bC[i] = (uint32_t)((nq * 32 + 16 * i + pr * 8 + l7) * 80 + kh * 16);
    }

    float acc[18][4];

    // Stage A: acc preloaded from PW (P-part + b1, exact fp32), K=128 M-part only
    #pragma unroll
    for (int mt = 0; mt < 2; ++mt) {
        int r_lo = m0 + mt * 64 + grp, r_hi = r_lo + 8;
        int s_lo = min(s0 + (r_lo >> 5), T_ - 1), s_hi = min(s0 + (r_hi >> 5), T_ - 1);
        const float* pwlo = g_PW + (s_lo * BB_ + (r_lo & 31)) * 144;
        const float* pwhi = g_PW + (s_hi * BB_ + (r_hi & 31)) * 144;
        #pragma unroll
        for (int j = 0; j < 9; ++j) {
            int n0 = nq * 72 + j * 8 + c0;
            float2 vlo = *(const float2*)(pwlo + n0);
            float2 vhi = *(const float2*)(pwhi + n0);
            acc[mt * 9 + j][0] = vlo.x; acc[mt * 9 + j][1] = vlo.y;
            acc[mt * 9 + j][2] = vhi.x; acc[mt * 9 + j][3] = vhi.y;
        }
    }
    gemm_stage<8, 9>((const char*)g_W1s, WBUF, su, acc, aH, aL, bAB, tid);
    __syncthreads();
    epi_relu(smem, acc, (const float*)0, m0, nq * 72, lane);
    __syncthreads();

    // Stage B: K=144 (9 ksteps), N=144
    #pragma unroll
    for (int i = 0; i < 18; ++i) { acc[i][0] = acc[i][1] = acc[i][2] = acc[i][3] = 0.f; }
    gemm_stage<9, 9>((const char*)g_W2s, WBUF, su, acc, aH, aL, bAB, tid);
    __syncthreads();
    epi_relu(smem, acc, sB2, m0, nq * 72, lane);
    __syncthreads();

    // Stage C: K=144 (9 ksteps), N=64 (acc[0..7] = 2 m-tiles x 4 n-tiles)
    #pragma unroll
    for (int i = 0; i < 8; ++i) { acc[i][0] = acc[i][1] = acc[i][2] = acc[i][3] = 0.f; }
    gemm_stage<9, 4>((const char*)g_W3s, WCH_C, su, acc, aH, aL, bC, tid);

    // X tile is dead now; init the aliased reduction buffer, then reduce
    __syncthreads();
    for (int i = tid; i < BB_ * O_; i += 256) sRed[i] = 0;
    __syncthreads();

    // final epilogue: sigmoid + max reduce
    {
        #pragma unroll
        for (int mt = 0; mt < 2; ++mt)
        #pragma unroll
        for (int rp = 0; rp < 2; ++rp) {
            int row = m0 + mt * 64 + grp + rp * 8;
            int sl = row >> 5, bb = row & 31;
            if (s0 + sl < T_) {
                #pragma unroll
                for (int j = 0; j < 4; ++j) {
                    int n0 = nq * 32 + j * 8 + c0;
                    float y0 = 1.f / (1.f + __expf(-5.f * (acc[mt * 4 + j][rp * 2 + 0] + sB3[n0])));
                    float y1 = 1.f / (1.f + __expf(-5.f * (acc[mt * 4 + j][rp * 2 + 1] + sB3[n0 + 1])));
                    atomicMax(&sRed[bb * O_ + n0], __float_as_int(y0));
                    atomicMax(&sRed[bb * O_ + n0 + 1], __float_as_int(y1));
                }
            }
        }
    }
    __syncthreads();
    for (int i = tid; i < BB_ * O_; i += 256) {
        int bb = i >> 6, o = i & 63;
        atomicMax((int*)(out + (bb * T_ + t) * O_ + o), sRed[i]);
    }
}

// ---------------- launch ----------------
extern "C" void kernel_launch(void* const* d_in, const int* in_sizes, int n_in,
                              void* d_out, int out_size) {
    const float* P  = (const float*)d_in[0];
    const float* W1 = (const float*)d_in[1];
    const float* b1 = (const float*)d_in[2];
    const float* W2 = (const float*)d_in[3];
    const float* b2 = (const float*)d_in[4];
    const float* W3 = (const float*)d_in[5];
    const float* b3 = (const float*)d_in[6];
    float* out = (float*)d_out;

    cudaFuncSetAttribute(mlp_main_kernel, cudaFuncAttributeMaxDynamicSharedMemorySize, SMEM_TOTAL);
    cudaFuncSetAttribute(compute_pw_kernel, cudaFuncAttributeMaxDynamicSharedMemorySize, PW_SMEM);

    prep_weights<<<(9 * 144 * NSTRIDE + 255) / 256, 256>>>(W1, W2, W3);
    compute_pre_kernel<<<(T_ * BB_ * D_) / 256, 256>>>(P);
    compute_pw_kernel<<<T_, 256, PW_SMEM>>>(P, W1, b1);
    init_out_kernel<<<(BB_ * T_ * O_ + 255) / 256, 256>>>(out);
    mlp_main_kernel<<<dim3(32, T_), 256, SMEM_TOTAL>>>(P, b2, b3, out);
}

// round 9
// speedup vs baseline: 4.0035x; 1.1965x over previous
#include <cuda_runtime.h>
#include <cuda_fp16.h>
#include <math.h>
#include <stdint.h>

#define BB_ 32
#define T_ 128
#define D_ 128
#define H_ 132
#define O_ 64

#define NSTRIDE 24                    // fp16 per n-row (48B): [16 k-vals][8B pad] -> ldmatrix conflict-free
#define WBUF (144 * 48)               // 6912 B per k-step chunk (N=144)
#define WCH_C (64 * 48)               // 3072 B stage-C chunk

// ---------------- SMEM layout ----------------
#define OFF_XH  0                     // 9 ksteps x 128 rows x 32B = 36864
#define OFF_XL  36864
#define OFF_W   73728                 // 3 x WBUF = 20736 -> 94464
#define OFF_B2  94464                 // 144 floats -> 95040
#define OFF_B3  95040                 // 64 floats  -> 95296
#define OFF_RED OFF_XH                // sRed (8192B) ALIASES X tile; used only after stage C
#define SMEM_TOTAL 95296              // x2 blocks = 190592 < 228KB/SM

// ---------------- device scratch ----------------
__device__ float g_pre4[T_ * 32 * BB_ * D_];   // [t][c][bb][d] prefix max over [t, t+4(c+1))
__device__ float g_PW[T_ * BB_ * 144];         // [s][bb][n]: P(s,bb)·W1[128:256] + b1 (exact fp32)
__device__ __half g_W1h[8 * 144 * NSTRIDE];    // [kstep][n][24], W1 rows 0..127 (M part), fp16
__device__ __half g_W2h[9 * 144 * NSTRIDE];
__device__ __half g_W3h[9 * 64 * NSTRIDE];

// ---------------- asm helpers ----------------
__device__ __forceinline__ void mma_f16(float d[4], const uint32_t a[4], const uint32_t b[2]) {
    asm volatile("mma.sync.aligned.m16n8k16.row.col.f32.f16.f16.f32 "
                 "{%0,%1,%2,%3}, {%4,%5,%6,%7}, {%8,%9}, {%0,%1,%2,%3};"
                 : "+f"(d[0]), "+f"(d[1]), "+f"(d[2]), "+f"(d[3])
                 : "r"(a[0]), "r"(a[1]), "r"(a[2]), "r"(a[3]), "r"(b[0]), "r"(b[1]));
}
__device__ __forceinline__ uint32_t smem_u32(const void* p) {
    uint32_t a;
    asm("{ .reg .u64 t; cvta.to.shared.u64 t, %1; cvt.u32.u64 %0, t; }" : "=r"(a) : "l"(p));
    return a;
}
#define CP16(dst, src) asm volatile("cp.async.ca.shared.global [%0], [%1], 16;" :: "r"(dst), "l"(src) : "memory")
#define CP_COMMIT()    asm volatile("cp.async.commit_group;" ::: "memory")
#define CP_WAIT1()     asm volatile("cp.async.wait_group 1;" ::: "memory")
#define LDSM4(r, a) asm volatile("ldmatrix.sync.aligned.m8n8.x4.shared.b16 {%0,%1,%2,%3}, [%4];" \
    : "=r"((r)[0]), "=r"((r)[1]), "=r"((r)[2]), "=r"((r)[3]) : "r"(a))
#define LDSM2(r, a) asm volatile("ldmatrix.sync.aligned.m8n8.x2.shared.b16 {%0,%1}, [%2];" \
    : "=r"((r)[0]), "=r"((r)[1]) : "r"(a))

// X element address with 16B-half swizzle (ldmatrix conflict-free); 128 rows/kstep
__device__ __forceinline__ int x_off(int ks, int row, int kk) {
    int phys = (kk >> 3) ^ ((row >> 2) & 1);
    return ks * 4096 + row * 32 + phys * 16 + (kk & 7) * 2;
}

// ---------------- prep: fp16 weights, N padded to 144, 48B n-stride ----------------
__global__ void prep_weights(const float* __restrict__ W1, const float* __restrict__ W2,
                             const float* __restrict__ W3) {
    int i = blockIdx.x * blockDim.x + threadIdx.x;
    if (i < 8 * 144 * NSTRIDE) {
        int ks = i / (144 * NSTRIDE), r = i % (144 * NSTRIDE);
        int n = r / NSTRIDE, kk = r % NSTRIDE;
        __half o = __float2half(0.f);
        if (kk < 16 && n < H_) o = __float2half(W1[(ks * 16 + kk) * H_ + n]);
        g_W1h[i] = o;
    }
    if (i < 9 * 144 * NSTRIDE) {
        int ks = i / (144 * NSTRIDE), r = i % (144 * NSTRIDE);
        int n = r / NSTRIDE, kk = r % NSTRIDE;
        int k = ks * 16 + kk;
        __half o = __float2half(0.f);
        if (kk < 16 && n < H_ && k < H_) o = __float2half(W2[k * H_ + n]);
        g_W2h[i] = o;
    }
    if (i < 9 * 64 * NSTRIDE) {
        int ks = i / (64 * NSTRIDE), r = i % (64 * NSTRIDE);
        int n = r / NSTRIDE, kk = r % NSTRIDE;
        int k = ks * 16 + kk;
        __half o = __float2half(0.f);
        if (kk < 16 && k < H_) o = __float2half(W3[k * O_ + n]);
        g_W3h[i] = o;
    }
}

// ---------------- prefix max at 4-step boundaries ----------------
__global__ void compute_pre_kernel(const float* __restrict__ P) {
    int idx = blockIdx.x * blockDim.x + threadIdx.x;
    int t = idx >> 12, bb = (idx >> 7) & 31, d = idx & 127;
    const float* Pp = P + bb * (T_ * D_) + d;
    float run = -3.4e38f;
    for (int s = t; s < T_; ++s) {
        run = fmaxf(run, Pp[s * D_]);
        int m = s - t + 1;
        if ((m & 3) == 0) {
            int ci = (m >> 2) - 1;
            if (ci < 32) g_pre4[((t * 32 + ci) * BB_ + bb) * D_ + d] = run;
        }
    }
}

// ---------------- PW[s][bb][n] = P(bb,s,:)·W1[128:256, n] + b1[n], exact fp32 ----------------
#define PW_SMEM (16384 + 73728)
__global__ void compute_pw_kernel(const float* __restrict__ P, const float* __restrict__ W1,
                                  const float* __restrict__ b1) {
    extern __shared__ char sm[];
    float* sP = (float*)sm;               // [32][128]
    float* sW = (float*)(sm + 16384);     // [128][144]
    int s = blockIdx.x;
    int tid = threadIdx.x;
    for (int i = tid; i < BB_ * D_; i += 256) {
        int bb = i >> 7, d = i & 127;
        sP[i] = P[(bb * T_ + s) * D_ + d];
    }
    for (int i = tid; i < 128 * 144; i += 256) {
        int d = i / 144, n = i % 144;
        sW[i] = (n < H_) ? W1[(128 + d) * H_ + n] : 0.f;
    }
    __syncthreads();
    for (int i = tid; i < BB_ * 72; i += 256) {
        int bb = i / 72, n = (i % 72) * 2;
        float ax = (n < H_) ? b1[n] : 0.f;
        float ay = (n + 1 < H_) ? b1[n + 1] : 0.f;
        const float* pr = sP + bb * 128;
        #pragma unroll 8
        for (int d = 0; d < 128; ++d) {
            float p = pr[d];
            ax += p * sW[d * 144 + n];
            ay += p * sW[d * 144 + n + 1];
        }
        float2 v; v.x = ax; v.y = ay;
        *(float2*)(g_PW + (s * BB_ + bb) * 144 + n) = v;
    }
}

__global__ void init_out_kernel(float* out) {
    int i = blockIdx.x * blockDim.x + threadIdx.x;
    if (i < BB_ * T_ * O_) out[i] = 0.f;
}

// ---------------- GEMM stage: 3-buffer cp.async (wait 1), fp16 2-pass (Xh+Xl)·W ----------------
template <int K16, int NT>
__device__ __forceinline__ void gemm_stage(const char* __restrict__ Wg, int chunk_bytes,
                                           uint32_t su, float (*acc)[4],
                                           const uint32_t aH[2], const uint32_t aL[2],
                                           const uint32_t* bOff, int tid) {
    for (int off = tid * 16; off < chunk_bytes; off += 4096)
        CP16(su + OFF_W + off, Wg + off);
    CP_COMMIT();
    for (int off = tid * 16; off < chunk_bytes; off += 4096)
        CP16(su + OFF_W + WBUF + off, Wg + chunk_bytes + off);
    CP_COMMIT();
    #pragma unroll 1
    for (int k = 0; k < K16; ++k) {
        CP_WAIT1();
        __syncthreads();
        if (k + 2 < K16) {
            const char* src = Wg + (size_t)(k + 2) * chunk_bytes;
            uint32_t dst = su + OFF_W + ((k + 2) % 3) * WBUF;
            for (int off = tid * 16; off < chunk_bytes; off += 4096)
                CP16(dst + off, src + off);
        }
        CP_COMMIT();
        uint32_t wb = su + OFF_W + (k % 3) * WBUF;
        uint32_t ah[2][4], al[2][4];
        LDSM4(ah[0], aH[0] + k * 4096);
        LDSM4(ah[1], aH[1] + k * 4096);
        LDSM4(al[0], aL[0] + k * 4096);
        LDSM4(al[1], aL[1] + k * 4096);
        uint32_t b[2 * NT];
        if (NT == 9) {
            LDSM4(b, wb + bOff[0]); LDSM4(b + 4, wb + bOff[1]);
            LDSM4(b + 8, wb + bOff[2]); LDSM4(b + 12, wb + bOff[3]);
            LDSM2(b + 16, wb + bOff[4]);
        } else {
            LDSM4(b, wb + bOff[0]); LDSM4(b + 4, wb + bOff[1]);
        }
        // pass 1: Xh·W
        #pragma unroll
        for (int j = 0; j < NT; ++j) { mma_f16(acc[j], ah[0], b + 2 * j); mma_f16(acc[NT + j], ah[1], b + 2 * j); }
        // pass 2: Xl·W  (X exact to ~22 bits; only W carries fp16 rounding)
        #pragma unroll
        for (int j = 0; j < NT; ++j) { mma_f16(acc[j], al[0], b + 2 * j); mma_f16(acc[NT + j], al[1], b + 2 * j); }
    }
}

// ---------------- relu epilogue: write fp16 hi/lo X tiles for next stage ----------------
__device__ __forceinline__ void epi_relu(char* smem, float (*acc)[4], const float* bias,
                                         int m0, int nbase, int lane) {
    char* xh = smem + OFF_XH;
    char* xl = smem + OFF_XL;
    const int grp = lane >> 2;
    const int c0 = 2 * (lane & 3);
    #pragma unroll
    for (int mt = 0; mt < 2; ++mt)
    #pragma unroll
    for (int j = 0; j < 9; ++j) {
        int n0 = nbase + j * 8 + c0;
        float bv0 = bias ? bias[n0] : 0.f;
        float bv1 = bias ? bias[n0 + 1] : 0.f;
        int ks = n0 >> 4, kk = n0 & 15;
        #pragma unroll
        for (int rp = 0; rp < 2; ++rp) {
            int row = m0 + mt * 64 + grp + rp * 8;
            float v0 = fmaxf(acc[mt * 9 + j][rp * 2 + 0] + bv0, 0.f);
            float v1 = fmaxf(acc[mt * 9 + j][rp * 2 + 1] + bv1, 0.f);
            __half h0 = __float2half(v0), h1 = __float2half(v1);
            __half2 hp; hp.x = h0; hp.y = h1;
            __half2 lp;
            lp.x = __float2half(v0 - __half2float(h0));
            lp.y = __float2half(v1 - __half2float(h1));
            int off = x_off(ks, row, kk);
            *(__half2*)(xh + off) = hp;
            *(__half2*)(xl + off) = lp;
        }
    }
}

// ---------------- main ----------------
__global__ void __launch_bounds__(256, 2)
mlp_main_kernel(const float* __restrict__ P,
                const float* __restrict__ b2, const float* __restrict__ b3,
                float* __restrict__ out) {
    const int t = blockIdx.y;
    const int c = blockIdx.x;
    const int nch = (T_ - t + 3) >> 2;
    if (c >= nch) return;
    const int s0 = t + 4 * c;

    extern __shared__ char smem[];
    uint32_t su = smem_u32(smem);
    const int tid = threadIdx.x;
    float* sB2 = (float*)(smem + OFF_B2);
    float* sB3 = (float*)(smem + OFF_B3);
    int* sRed = (int*)(smem + OFF_RED);    // ALIASES X tile; valid only after stage C

    for (int i = tid; i < 144; i += 256) sB2[i] = (i < H_) ? b2[i] : 0.f;
    if (tid < 64) sB3[tid] = b3[tid];

    // feature build: rows r = sl*32+bb (sl 0..3); K cols [0,128) = running max, fp16 hi/lo
    {
        int d = tid & 127, half = tid >> 7;
        char* xh = smem + OFF_XH;
        char* xl = smem + OFF_XL;
        int ksM = d >> 4, kk = d & 15;
        for (int bb = half * 16; bb < half * 16 + 16; ++bb) {
            float run = (c > 0) ? g_pre4[((t * 32 + (c - 1)) * BB_ + bb) * D_ + d] : -3.4e38f;
            #pragma unroll
            for (int sl = 0; sl < 4; ++sl) {
                int s = s0 + sl;
                if (s < T_) run = fmaxf(run, P[(bb * T_ + s) * D_ + d]);
                int row = sl * 32 + bb;
                int offM = x_off(ksM, row, kk);
                __half hm = __float2half(run);
                *(__half*)(xh + offM) = hm;
                *(__half*)(xl + offM) = __float2half(run - __half2float(hm));
            }
        }
    }
    __syncthreads();

    const int wid = tid >> 5, lane = tid & 31;
    const int mq = wid >> 1, nq = wid & 1;      // 4 m-quads x 2 n-halves; m-tiles at m0, m0+64
    const int m0 = mq * 16;
    const int grp = lane >> 2, c0 = 2 * (lane & 3);

    // per-lane ldmatrix addresses
    uint32_t aH[2], aL[2], bAB[5], bC[2];
    {
        int l15 = lane & 15, chnk = lane >> 4;
        #pragma unroll
        for (int mt = 0; mt < 2; ++mt) {
            int row = m0 + mt * 64 + l15;
            int phys = chnk ^ ((row >> 2) & 1);
            aH[mt] = su + OFF_XH + row * 32 + phys * 16;
            aL[mt] = aH[mt] + (OFF_XL - OFF_XH);
        }
        int l7 = lane & 7, kh = (lane >> 3) & 1, pr = (lane >> 4) & 1;
        #pragma unroll
        for (int i = 0; i < 4; ++i)
            bAB[i] = (uint32_t)((nq * 72 + 16 * i + pr * 8 + l7) * 48 + kh * 16);
        bAB[4] = (uint32_t)((nq * 72 + 64 + l7) * 48 + kh * 16);
        #pragma unroll
        for (int i = 0; i < 2; ++i)
            bC[i] = (uint32_t)((nq * 32 + 16 * i + pr * 8 + l7) * 48 + kh * 16);
    }

    float acc[18][4];

    // Stage A: acc preloaded from PW (P-part + b1, exact fp32), K=128 M-part only
    #pragma unroll
    for (int mt = 0; mt < 2; ++mt) {
        int r_lo = m0 + mt * 64 + grp, r_hi = r_lo + 8;
        int s_lo = min(s0 + (r_lo >> 5), T_ - 1), s_hi = min(s0 + (r_hi >> 5), T_ - 1);
        const float* pwlo = g_PW + (s_lo * BB_ + (r_lo & 31)) * 144;
        const float* pwhi = g_PW + (s_hi * BB_ + (r_hi & 31)) * 144;
        #pragma unroll
        for (int j = 0; j < 9; ++j) {
            int n0 = nq * 72 + j * 8 + c0;
            float2 vlo = *(const float2*)(pwlo + n0);
            float2 vhi = *(const float2*)(pwhi + n0);
            acc[mt * 9 + j][0] = vlo.x; acc[mt * 9 + j][1] = vlo.y;
            acc[mt * 9 + j][2] = vhi.x; acc[mt * 9 + j][3] = vhi.y;
        }
    }
    gemm_stage<8, 9>((const char*)g_W1h, WBUF, su, acc, aH, aL, bAB, tid);
    __syncthreads();
    epi_relu(smem, acc, (const float*)0, m0, nq * 72, lane);
    __syncthreads();

    // Stage B: K=144 (9 ksteps), N=144
    #pragma unroll
    for (int i = 0; i < 18; ++i) { acc[i][0] = acc[i][1] = acc[i][2] = acc[i][3] = 0.f; }
    gemm_stage<9, 9>((const char*)g_W2h, WBUF, su, acc, aH, aL, bAB, tid);
    __syncthreads();
    epi_relu(smem, acc, sB2, m0, nq * 72, lane);
    __syncthreads();

    // Stage C: K=144 (9 ksteps), N=64 (acc[0..7] = 2 m-tiles x 4 n-tiles)
    #pragma unroll
    for (int i = 0; i < 8; ++i) { acc[i][0] = acc[i][1] = acc[i][2] = acc[i][3] = 0.f; }
    gemm_stage<9, 4>((const char*)g_W3h, WCH_C, su, acc, aH, aL, bC, tid);

    // X tile is dead now; init the aliased reduction buffer, then reduce
    __syncthreads();
    for (int i = tid; i < BB_ * O_; i += 256) sRed[i] = 0;
    __syncthreads();

    // final epilogue: sigmoid + max reduce
    {
        #pragma unroll
        for (int mt = 0; mt < 2; ++mt)
        #pragma unroll
        for (int rp = 0; rp < 2; ++rp) {
            int row = m0 + mt * 64 + grp + rp * 8;
            int sl = row >> 5, bb = row & 31;
            if (s0 + sl < T_) {
                #pragma unroll
                for (int j = 0; j < 4; ++j) {
                    int n0 = nq * 32 + j * 8 + c0;
                    float y0 = 1.f / (1.f + __expf(-5.f * (acc[mt * 4 + j][rp * 2 + 0] + sB3[n0])));
                    float y1 = 1.f / (1.f + __expf(-5.f * (acc[mt * 4 + j][rp * 2 + 1] + sB3[n0 + 1])));
                    atomicMax(&sRed[bb * O_ + n0], __float_as_int(y0));
                    atomicMax(&sRed[bb * O_ + n0 + 1], __float_as_int(y1));
                }
            }
        }
    }
    __syncthreads();
    for (int i = tid; i < BB_ * O_; i += 256) {
        int bb = i >> 6, o = i & 63;
        atomicMax((int*)(out + (bb * T_ + t) * O_ + o), sRed[i]);
    }
}

// ---------------- launch ----------------
extern "C" void kernel_launch(void* const* d_in, const int* in_sizes, int n_in,
                              void* d_out, int out_size) {
    const float* P  = (const float*)d_in[0];
    const float* W1 = (const float*)d_in[1];
    const float* b1 = (const float*)d_in[2];
    const float* W2 = (const float*)d_in[3];
    const float* b2 = (const float*)d_in[4];
    const float* W3 = (const float*)d_in[5];
    const float* b3 = (const float*)d_in[6];
    float* out = (float*)d_out;

    cudaFuncSetAttribute(mlp_main_kernel, cudaFuncAttributeMaxDynamicSharedMemorySize, SMEM_TOTAL);
    cudaFuncSetAttribute(compute_pw_kernel, cudaFuncAttributeMaxDynamicSharedMemorySize, PW_SMEM);

    prep_weights<<<(9 * 144 * NSTRIDE + 255) / 256, 256>>>(W1, W2, W3);
    compute_pre_kernel<<<(T_ * BB_ * D_) / 256, 256>>>(P);
    compute_pw_kernel<<<T_, 256, PW_SMEM>>>(P, W1, b1);
    init_out_kernel<<<(BB_ * T_ * O_ + 255) / 256, 256>>>(out);
    mlp_main_kernel<<<dim3(32, T_), 256, SMEM_TOTAL>>>(P, b2, b3, out);
}

// round 10
// speedup vs baseline: 5.0907x; 1.2716x over previous
#include <cuda_runtime.h>
#include <cuda_fp16.h>
#include <math.h>
#include <stdint.h>

#define BB_ 32
#define T_ 128
#define D_ 128
#define H_ 132
#define O_ 64

#define NSTRIDE 24                    // fp16 per n-row (48B): [16 k-vals][8B pad] -> ldmatrix conflict-free
#define WBUF (144 * 48)               // 6912 B per k-step chunk (N=144)
#define WCH_C (64 * 48)               // 3072 B stage-C chunk

// ---------------- SMEM layout ----------------
#define OFF_XH  0                     // 9 ksteps x 128 rows x 32B = 36864
#define OFF_W   36864                 // 3 x WBUF = 20736 -> 57600
#define OFF_B2  57600                 // 144 floats -> 58176
#define OFF_B3  58176                 // 64 floats  -> 58432
#define OFF_RED OFF_XH                // sRed (8192B) ALIASES X tile; used only after stage C
#define SMEM_TOTAL 58432              // x2 blocks = 116864, lots of L1 headroom

// ---------------- device scratch ----------------
__device__ float g_pre4[T_ * 32 * BB_ * D_];   // [t][c][bb][d] prefix max over [t, t+4(c+1))
__device__ float g_PW[T_ * BB_ * 144];         // [s][bb][n]: P(s,bb)·W1[128:256] + b1 (exact fp32)
__device__ __half g_W1h[8 * 144 * NSTRIDE];    // [kstep][n][24], W1 rows 0..127 (M part), fp16
__device__ __half g_W2h[9 * 144 * NSTRIDE];
__device__ __half g_W3h[9 * 64 * NSTRIDE];

// ---------------- asm helpers ----------------
__device__ __forceinline__ void mma_f16(float d[4], const uint32_t a[4], const uint32_t b[2]) {
    asm volatile("mma.sync.aligned.m16n8k16.row.col.f32.f16.f16.f32 "
                 "{%0,%1,%2,%3}, {%4,%5,%6,%7}, {%8,%9}, {%0,%1,%2,%3};"
                 : "+f"(d[0]), "+f"(d[1]), "+f"(d[2]), "+f"(d[3])
                 : "r"(a[0]), "r"(a[1]), "r"(a[2]), "r"(a[3]), "r"(b[0]), "r"(b[1]));
}
__device__ __forceinline__ uint32_t smem_u32(const void* p) {
    uint32_t a;
    asm("{ .reg .u64 t; cvta.to.shared.u64 t, %1; cvt.u32.u64 %0, t; }" : "=r"(a) : "l"(p));
    return a;
}
#define CP16(dst, src) asm volatile("cp.async.ca.shared.global [%0], [%1], 16;" :: "r"(dst), "l"(src) : "memory")
#define CP_COMMIT()    asm volatile("cp.async.commit_group;" ::: "memory")
#define CP_WAIT1()     asm volatile("cp.async.wait_group 1;" ::: "memory")
#define LDSM4(r, a) asm volatile("ldmatrix.sync.aligned.m8n8.x4.shared.b16 {%0,%1,%2,%3}, [%4];" \
    : "=r"((r)[0]), "=r"((r)[1]), "=r"((r)[2]), "=r"((r)[3]) : "r"(a))
#define LDSM2(r, a) asm volatile("ldmatrix.sync.aligned.m8n8.x2.shared.b16 {%0,%1}, [%2];" \
    : "=r"((r)[0]), "=r"((r)[1]) : "r"(a))

// X element address with 16B-half swizzle (ldmatrix conflict-free); 128 rows/kstep
__device__ __forceinline__ int x_off(int ks, int row, int kk) {
    int phys = (kk >> 3) ^ ((row >> 2) & 1);
    return ks * 4096 + row * 32 + phys * 16 + (kk & 7) * 2;
}

// ---------------- prep: fp16 weights, N padded to 144, 48B n-stride ----------------
__global__ void prep_weights(const float* __restrict__ W1, const float* __restrict__ W2,
                             const float* __restrict__ W3) {
    int i = blockIdx.x * blockDim.x + threadIdx.x;
    if (i < 8 * 144 * NSTRIDE) {
        int ks = i / (144 * NSTRIDE), r = i % (144 * NSTRIDE);
        int n = r / NSTRIDE, kk = r % NSTRIDE;
        __half o = __float2half(0.f);
        if (kk < 16 && n < H_) o = __float2half(W1[(ks * 16 + kk) * H_ + n]);
        g_W1h[i] = o;
    }
    if (i < 9 * 144 * NSTRIDE) {
        int ks = i / (144 * NSTRIDE), r = i % (144 * NSTRIDE);
        int n = r / NSTRIDE, kk = r % NSTRIDE;
        int k = ks * 16 + kk;
        __half o = __float2half(0.f);
        if (kk < 16 && n < H_ && k < H_) o = __float2half(W2[k * H_ + n]);
        g_W2h[i] = o;
    }
    if (i < 9 * 64 * NSTRIDE) {
        int ks = i / (64 * NSTRIDE), r = i % (64 * NSTRIDE);
        int n = r / NSTRIDE, kk = r % NSTRIDE;
        int k = ks * 16 + kk;
        __half o = __float2half(0.f);
        if (kk < 16 && k < H_) o = __float2half(W3[k * O_ + n]);
        g_W3h[i] = o;
    }
}

// ---------------- prefix max at 4-step boundaries ----------------
__global__ void compute_pre_kernel(const float* __restrict__ P) {
    int idx = blockIdx.x * blockDim.x + threadIdx.x;
    int t = idx >> 12, bb = (idx >> 7) & 31, d = idx & 127;
    const float* Pp = P + bb * (T_ * D_) + d;
    float run = -3.4e38f;
    for (int s = t; s < T_; ++s) {
        run = fmaxf(run, Pp[s * D_]);
        int m = s - t + 1;
        if ((m & 3) == 0) {
            int ci = (m >> 2) - 1;
            if (ci < 32) g_pre4[((t * 32 + ci) * BB_ + bb) * D_ + d] = run;
        }
    }
}

// ---------------- PW[s][bb][n] = P(bb,s,:)·W1[128:256, n] + b1[n], exact fp32 ----------------
#define PW_SMEM (16384 + 73728)
__global__ void compute_pw_kernel(const float* __restrict__ P, const float* __restrict__ W1,
                                  const float* __restrict__ b1) {
    extern __shared__ char sm[];
    float* sP = (float*)sm;               // [32][128]
    float* sW = (float*)(sm + 16384);     // [128][144]
    int s = blockIdx.x;
    int tid = threadIdx.x;
    for (int i = tid; i < BB_ * D_; i += 256) {
        int bb = i >> 7, d = i & 127;
        sP[i] = P[(bb * T_ + s) * D_ + d];
    }
    for (int i = tid; i < 128 * 144; i += 256) {
        int d = i / 144, n = i % 144;
        sW[i] = (n < H_) ? W1[(128 + d) * H_ + n] : 0.f;
    }
    __syncthreads();
    for (int i = tid; i < BB_ * 72; i += 256) {
        int bb = i / 72, n = (i % 72) * 2;
        float ax = (n < H_) ? b1[n] : 0.f;
        float ay = (n + 1 < H_) ? b1[n + 1] : 0.f;
        const float* pr = sP + bb * 128;
        #pragma unroll 8
        for (int d = 0; d < 128; ++d) {
            float p = pr[d];
            ax += p * sW[d * 144 + n];
            ay += p * sW[d * 144 + n + 1];
        }
        float2 v; v.x = ax; v.y = ay;
        *(float2*)(g_PW + (s * BB_ + bb) * 144 + n) = v;
    }
}

__global__ void init_out_kernel(float* out) {
    int i = blockIdx.x * blockDim.x + threadIdx.x;
    if (i < BB_ * T_ * O_) out[i] = 0.f;
}

// ---------------- GEMM stage: 3-buffer cp.async (wait 1), 1-pass fp16 ----------------
template <int K16, int NT>
__device__ __forceinline__ void gemm_stage(const char* __restrict__ Wg, int chunk_bytes,
                                           uint32_t su, float (*acc)[4],
                                           const uint32_t aH[2],
                                           const uint32_t* bOff, int tid) {
    for (int off = tid * 16; off < chunk_bytes; off += 4096)
        CP16(su + OFF_W + off, Wg + off);
    CP_COMMIT();
    for (int off = tid * 16; off < chunk_bytes; off += 4096)
        CP16(su + OFF_W + WBUF + off, Wg + chunk_bytes + off);
    CP_COMMIT();
    #pragma unroll 1
    for (int k = 0; k < K16; ++k) {
        CP_WAIT1();
        __syncthreads();
        if (k + 2 < K16) {
            const char* src = Wg + (size_t)(k + 2) * chunk_bytes;
            uint32_t dst = su + OFF_W + ((k + 2) % 3) * WBUF;
            for (int off = tid * 16; off < chunk_bytes; off += 4096)
                CP16(dst + off, src + off);
        }
        CP_COMMIT();
        uint32_t wb = su + OFF_W + (k % 3) * WBUF;
        uint32_t ah[2][4];
        LDSM4(ah[0], aH[0] + k * 4096);
        LDSM4(ah[1], aH[1] + k * 4096);
        uint32_t b[2 * NT];
        if (NT == 9) {
            LDSM4(b, wb + bOff[0]); LDSM4(b + 4, wb + bOff[1]);
            LDSM4(b + 8, wb + bOff[2]); LDSM4(b + 12, wb + bOff[3]);
            LDSM2(b + 16, wb + bOff[4]);
        } else {
            LDSM4(b, wb + bOff[0]); LDSM4(b + 4, wb + bOff[1]);
        }
        #pragma unroll
        for (int j = 0; j < NT; ++j) { mma_f16(acc[j], ah[0], b + 2 * j); mma_f16(acc[NT + j], ah[1], b + 2 * j); }
    }
}

// ---------------- relu epilogue: write fp16 X tile for next stage ----------------
__device__ __forceinline__ void epi_relu(char* smem, float (*acc)[4], const float* bias,
                                         int m0, int nbase, int lane) {
    char* xh = smem + OFF_XH;
    const int grp = lane >> 2;
    const int c0 = 2 * (lane & 3);
    #pragma unroll
    for (int mt = 0; mt < 2; ++mt)
    #pragma unroll
    for (int j = 0; j < 9; ++j) {
        int n0 = nbase + j * 8 + c0;
        float bv0 = bias ? bias[n0] : 0.f;
        float bv1 = bias ? bias[n0 + 1] : 0.f;
        int ks = n0 >> 4, kk = n0 & 15;
        #pragma unroll
        for (int rp = 0; rp < 2; ++rp) {
            int row = m0 + mt * 64 + grp + rp * 8;
            float v0 = fmaxf(acc[mt * 9 + j][rp * 2 + 0] + bv0, 0.f);
            float v1 = fmaxf(acc[mt * 9 + j][rp * 2 + 1] + bv1, 0.f);
            __half2 hp; hp.x = __float2half(v0); hp.y = __float2half(v1);
            *(__half2*)(xh + x_off(ks, row, kk)) = hp;
        }
    }
}

// ---------------- main ----------------
__global__ void __launch_bounds__(256, 2)
mlp_main_kernel(const float* __restrict__ P,
                const float* __restrict__ b2, const float* __restrict__ b3,
                float* __restrict__ out) {
    const int t = blockIdx.y;
    const int c = blockIdx.x;
    const int nch = (T_ - t + 3) >> 2;
    if (c >= nch) return;
    const int s0 = t + 4 * c;

    extern __shared__ char smem[];
    uint32_t su = smem_u32(smem);
    const int tid = threadIdx.x;
    float* sB2 = (float*)(smem + OFF_B2);
    float* sB3 = (float*)(smem + OFF_B3);
    int* sRed = (int*)(smem + OFF_RED);    // ALIASES X tile; valid only after stage C

    for (int i = tid; i < 144; i += 256) sB2[i] = (i < H_) ? b2[i] : 0.f;
    if (tid < 64) sB3[tid] = b3[tid];

    // feature build: rows r = sl*32+bb (sl 0..3); K cols [0,128) = running max, fp16
    {
        int d = tid & 127, half = tid >> 7;
        char* xh = smem + OFF_XH;
        int ksM = d >> 4, kk = d & 15;
        for (int bb = half * 16; bb < half * 16 + 16; ++bb) {
            float run = (c > 0) ? g_pre4[((t * 32 + (c - 1)) * BB_ + bb) * D_ + d] : -3.4e38f;
            #pragma unroll
            for (int sl = 0; sl < 4; ++sl) {
                int s = s0 + sl;
                if (s < T_) run = fmaxf(run, P[(bb * T_ + s) * D_ + d]);
                int row = sl * 32 + bb;
                *(__half*)(xh + x_off(ksM, row, kk)) = __float2half(run);
            }
        }
    }
    __syncthreads();

    const int wid = tid >> 5, lane = tid & 31;
    const int mq = wid >> 1, nq = wid & 1;      // 4 m-quads x 2 n-halves; m-tiles at m0, m0+64
    const int m0 = mq * 16;
    const int grp = lane >> 2, c0 = 2 * (lane & 3);

    // per-lane ldmatrix addresses
    uint32_t aH[2], bAB[5], bC[2];
    {
        int l15 = lane & 15, chnk = lane >> 4;
        #pragma unroll
        for (int mt = 0; mt < 2; ++mt) {
            int row = m0 + mt * 64 + l15;
            int phys = chnk ^ ((row >> 2) & 1);
            aH[mt] = su + OFF_XH + row * 32 + phys * 16;
        }
        int l7 = lane & 7, kh = (lane >> 3) & 1, pr = (lane >> 4) & 1;
        #pragma unroll
        for (int i = 0; i < 4; ++i)
            bAB[i] = (uint32_t)((nq * 72 + 16 * i + pr * 8 + l7) * 48 + kh * 16);
        bAB[4] = (uint32_t)((nq * 72 + 64 + l7) * 48 + kh * 16);
        #pragma unroll
        for (int i = 0; i < 2; ++i)
            bC[i] = (uint32_t)((nq * 32 + 16 * i + pr * 8 + l7) * 48 + kh * 16);
    }

    float acc[18][4];

    // Stage A: acc preloaded from PW (P-part + b1, exact fp32), K=128 M-part only
    #pragma unroll
    for (int mt = 0; mt < 2; ++mt) {
        int r_lo = m0 + mt * 64 + grp, r_hi = r_lo + 8;
        int s_lo = min(s0 + (r_lo >> 5), T_ - 1), s_hi = min(s0 + (r_hi >> 5), T_ - 1);
        const float* pwlo = g_PW + (s_lo * BB_ + (r_lo & 31)) * 144;
        const float* pwhi = g_PW + (s_hi * BB_ + (r_hi & 31)) * 144;
        #pragma unroll
        for (int j = 0; j < 9; ++j) {
            int n0 = nq * 72 + j * 8 + c0;
            float2 vlo = *(const float2*)(pwlo + n0);
            float2 vhi = *(const float2*)(pwhi + n0);
            acc[mt * 9 + j][0] = vlo.x; acc[mt * 9 + j][1] = vlo.y;
            acc[mt * 9 + j][2] = vhi.x; acc[mt * 9 + j][3] = vhi.y;
        }
    }
    gemm_stage<8, 9>((const char*)g_W1h, WBUF, su, acc, aH, bAB, tid);
    __syncthreads();
    epi_relu(smem, acc, (const float*)0, m0, nq * 72, lane);
    __syncthreads();

    // Stage B: K=144 (9 ksteps), N=144
    #pragma unroll
    for (int i = 0; i < 18; ++i) { acc[i][0] = acc[i][1] = acc[i][2] = acc[i][3] = 0.f; }
    gemm_stage<9, 9>((const char*)g_W2h, WBUF, su, acc, aH, bAB, tid);
    __syncthreads();
    epi_relu(smem, acc, sB2, m0, nq * 72, lane);
    __syncthreads();

    // Stage C: K=144 (9 ksteps), N=64 (acc[0..7] = 2 m-tiles x 4 n-tiles)
    #pragma unroll
    for (int i = 0; i < 8; ++i) { acc[i][0] = acc[i][1] = acc[i][2] = acc[i][3] = 0.f; }
    gemm_stage<9, 4>((const char*)g_W3h, WCH_C, su, acc, aH, bC, tid);

    // X tile is dead now; init the aliased reduction buffer, then reduce
    __syncthreads();
    for (int i = tid; i < BB_ * O_; i += 256) sRed[i] = 0;
    __syncthreads();

    // final epilogue: sigmoid + max reduce
    {
        #pragma unroll
        for (int mt = 0; mt < 2; ++mt)
        #pragma unroll
        for (int rp = 0; rp < 2; ++rp) {
            int row = m0 + mt * 64 + grp + rp * 8;
            int sl = row >> 5, bb = row & 31;
            if (s0 + sl < T_) {
                #pragma unroll
                for (int j = 0; j < 4; ++j) {
                    int n0 = nq * 32 + j * 8 + c0;
                    float y0 = 1.f / (1.f + __expf(-5.f * (acc[mt * 4 + j][rp * 2 + 0] + sB3[n0])));
                    float y1 = 1.f / (1.f + __expf(-5.f * (acc[mt * 4 + j][rp * 2 + 1] + sB3[n0 + 1])));
                    atomicMax(&sRed[bb * O_ + n0], __float_as_int(y0));
                    atomicMax(&sRed[bb * O_ + n0 + 1], __float_as_int(y1));
                }
            }
        }
    }
    __syncthreads();
    for (int i = tid; i < BB_ * O_; i += 256) {
        int bb = i >> 6, o = i & 63;
        atomicMax((int*)(out + (bb * T_ + t) * O_ + o), sRed[i]);
    }
}

// ---------------- launch ----------------
extern "C" void kernel_launch(void* const* d_in, const int* in_sizes, int n_in,
                              void* d_out, int out_size) {
    const float* P  = (const float*)d_in[0];
    const float* W1 = (const float*)d_in[1];
    const float* b1 = (const float*)d_in[2];
    const float* W2 = (const float*)d_in[3];
    const float* b2 = (const float*)d_in[4];
    const float* W3 = (const float*)d_in[5];
    const float* b3 = (const float*)d_in[6];
    float* out = (float*)d_out;

    cudaFuncSetAttribute(mlp_main_kernel, cudaFuncAttributeMaxDynamicSharedMemorySize, SMEM_TOTAL);
    cudaFuncSetAttribute(compute_pw_kernel, cudaFuncAttributeMaxDynamicSharedMemorySize, PW_SMEM);

    prep_weights<<<(9 * 144 * NSTRIDE + 255) / 256, 256>>>(W1, W2, W3);
    compute_pre_kernel<<<(T_ * BB_ * D_) / 256, 256>>>(P);
    compute_pw_kernel<<<T_, 256, PW_SMEM>>>(P, W1, b1);
    init_out_kernel<<<(BB_ * T_ * O_ + 255) / 256, 256>>>(out);
    mlp_main_kernel<<<dim3(32, T_), 256, SMEM_TOTAL>>>(P, b2, b3, out);
}

// round 11
// speedup vs baseline: 5.6248x; 1.1049x over previous
#include <cuda_runtime.h>
#include <cuda_fp16.h>
#include <math.h>
#include <stdint.h>

#define BB_ 32
#define T_ 128
#define D_ 128
#define H_ 132
#define O_ 64

#define NSTRIDE 24                    // fp16 per n-row (48B): [16 k-vals][8B pad] -> ldmatrix conflict-free
#define WCH_AB (144 * 48)             // 6912 B per k-step chunk (N=144)
#define WCH_C  (64 * 48)              // 3072 B per k-step chunk (N=64)
#define WBYTES_A (8 * WCH_AB)         // 55296
#define WBYTES_B (9 * WCH_AB)         // 62208
#define WBYTES_C (9 * WCH_C)          // 27648

// ---------------- SMEM layout ----------------
#define OFF_X   0                     // 9 ksteps x 128 rows x 32B = 36864
#define OFF_W   36864                 // whole-stage weights, max 62208 -> 99072
#define OFF_B2  99072                 // 144 floats -> 99648
#define OFF_B3  99648                 // 64 floats  -> 99904
#define OFF_RED OFF_X                 // sRed (8192B) ALIASES X tile; used only after stage C
#define SMEM_TOTAL 99904              // x2 blocks = 199808 < 228KB/SM

#define NBLK 2112                     // sum_t ceil((128-t)/4)

// ---------------- device scratch ----------------
__device__ float g_pre4[T_ * 32 * BB_ * D_];   // [t][c][bb][d] prefix max over [t, t+4(c+1))
__device__ float g_PW[T_ * BB_ * 144];         // [s][bb][n]: P(s,bb)·W1[128:256] + b1 (exact fp32)
__device__ __half g_W1h[8 * 144 * NSTRIDE];    // [kstep][n][24], W1 rows 0..127 (M part), fp16
__device__ __half g_W2h[9 * 144 * NSTRIDE];
__device__ __half g_W3h[9 * 64 * NSTRIDE];
__device__ int g_map[NBLK];                    // packed (t<<8)|c

// ---------------- asm helpers ----------------
__device__ __forceinline__ void mma_f16(float d[4], const uint32_t a[4], const uint32_t b[2]) {
    asm volatile("mma.sync.aligned.m16n8k16.row.col.f32.f16.f16.f32 "
                 "{%0,%1,%2,%3}, {%4,%5,%6,%7}, {%8,%9}, {%0,%1,%2,%3};"
                 : "+f"(d[0]), "+f"(d[1]), "+f"(d[2]), "+f"(d[3])
                 : "r"(a[0]), "r"(a[1]), "r"(a[2]), "r"(a[3]), "r"(b[0]), "r"(b[1]));
}
__device__ __forceinline__ uint32_t smem_u32(const void* p) {
    uint32_t a;
    asm("{ .reg .u64 t; cvta.to.shared.u64 t, %1; cvt.u32.u64 %0, t; }" : "=r"(a) : "l"(p));
    return a;
}
#define CP16(dst, src) asm volatile("cp.async.ca.shared.global [%0], [%1], 16;" :: "r"(dst), "l"(src) : "memory")
#define CP_COMMIT()    asm volatile("cp.async.commit_group;" ::: "memory")
#define CP_WAIT0()     asm volatile("cp.async.wait_group 0;" ::: "memory")
#define LDSM4(r, a) asm volatile("ldmatrix.sync.aligned.m8n8.x4.shared.b16 {%0,%1,%2,%3}, [%4];" \
    : "=r"((r)[0]), "=r"((r)[1]), "=r"((r)[2]), "=r"((r)[3]) : "r"(a))
#define LDSM2(r, a) asm volatile("ldmatrix.sync.aligned.m8n8.x2.shared.b16 {%0,%1}, [%2];" \
    : "=r"((r)[0]), "=r"((r)[1]) : "r"(a))

// X element address with 16B-half swizzle (ldmatrix conflict-free); 128 rows/kstep
__device__ __forceinline__ int x_off(int ks, int row, int kk) {
    int phys = (kk >> 3) ^ ((row >> 2) & 1);
    return ks * 4096 + row * 32 + phys * 16 + (kk & 7) * 2;
}

// ---------------- prep: fp16 weights, N padded to 144, 48B n-stride ----------------
__global__ void prep_weights(const float* __restrict__ W1, const float* __restrict__ W2,
                             const float* __restrict__ W3) {
    int i = blockIdx.x * blockDim.x + threadIdx.x;
    if (i < 8 * 144 * NSTRIDE) {
        int ks = i / (144 * NSTRIDE), r = i % (144 * NSTRIDE);
        int n = r / NSTRIDE, kk = r % NSTRIDE;
        __half o = __float2half(0.f);
        if (kk < 16 && n < H_) o = __float2half(W1[(ks * 16 + kk) * H_ + n]);
        g_W1h[i] = o;
    }
    if (i < 9 * 144 * NSTRIDE) {
        int ks = i / (144 * NSTRIDE), r = i % (144 * NSTRIDE);
        int n = r / NSTRIDE, kk = r % NSTRIDE;
        int k = ks * 16 + kk;
        __half o = __float2half(0.f);
        if (kk < 16 && n < H_ && k < H_) o = __float2half(W2[k * H_ + n]);
        g_W2h[i] = o;
    }
    if (i < 9 * 64 * NSTRIDE) {
        int ks = i / (64 * NSTRIDE), r = i % (64 * NSTRIDE);
        int n = r / NSTRIDE, kk = r % NSTRIDE;
        int k = ks * 16 + kk;
        __half o = __float2half(0.f);
        if (kk < 16 && k < H_) o = __float2half(W3[k * O_ + n]);
        g_W3h[i] = o;
    }
}

// ---------------- block map: linear index -> (t, c) ----------------
__global__ void build_map() {
    int t = threadIdx.x;               // 128 threads
    int start = 0;
    for (int u = 0; u < t; ++u) start += (131 - u) >> 2;
    int nch = (131 - t) >> 2;
    for (int c2 = 0; c2 < nch; ++c2) g_map[start + c2] = (t << 8) | c2;
}

// ---------------- prefix max at 4-step boundaries (+ out init folded in) ----------------
__global__ void compute_pre_kernel(const float* __restrict__ P, float* __restrict__ out) {
    int idx = blockIdx.x * blockDim.x + threadIdx.x;
    if (idx < BB_ * T_ * O_) out[idx] = 0.f;
    int t = idx >> 12, bb = (idx >> 7) & 31, d = idx & 127;
    const float* Pp = P + bb * (T_ * D_) + d;
    float run = -3.4e38f;
    for (int s = t; s < T_; ++s) {
        run = fmaxf(run, Pp[s * D_]);
        int m = s - t + 1;
        if ((m & 3) == 0) {
            int ci = (m >> 2) - 1;
            if (ci < 32) g_pre4[((t * 32 + ci) * BB_ + bb) * D_ + d] = run;
        }
    }
}

// ---------------- PW[s][bb][n] = P(bb,s,:)·W1[128:256, n] + b1[n], exact fp32 ----------------
#define PW_SMEM (16384 + 73728)
__global__ void compute_pw_kernel(const float* __restrict__ P, const float* __restrict__ W1,
                                  const float* __restrict__ b1) {
    extern __shared__ char sm[];
    float* sP = (float*)sm;               // [32][128]
    float* sW = (float*)(sm + 16384);     // [128][144]
    int s = blockIdx.x;
    int tid = threadIdx.x;
    for (int i = tid; i < BB_ * D_; i += 256) {
        int bb = i >> 7, d = i & 127;
        sP[i] = P[(bb * T_ + s) * D_ + d];
    }
    for (int i = tid; i < 128 * 144; i += 256) {
        int d = i / 144, n = i % 144;
        sW[i] = (n < H_) ? W1[(128 + d) * H_ + n] : 0.f;
    }
    __syncthreads();
    for (int i = tid; i < BB_ * 72; i += 256) {
        int bb = i / 72, n = (i % 72) * 2;
        float ax = (n < H_) ? b1[n] : 0.f;
        float ay = (n + 1 < H_) ? b1[n + 1] : 0.f;
        const float* pr = sP + bb * 128;
        #pragma unroll 8
        for (int d = 0; d < 128; ++d) {
            float p = pr[d];
            ax += p * sW[d * 144 + n];
            ay += p * sW[d * 144 + n + 1];
        }
        float2 v; v.x = ax; v.y = ay;
        *(float2*)(g_PW + (s * BB_ + bb) * 144 + n) = v;
    }
}

// ---------------- barrier-free GEMM stage: whole-stage weights resident in smem ----------------
template <int K16, int NT, int CHUNK>
__device__ __forceinline__ void gemm_stage(uint32_t su, float (*acc)[4],
                                           const uint32_t aH[2], const uint32_t* bOff) {
    #pragma unroll
    for (int k = 0; k < K16; ++k) {
        uint32_t wb = su + OFF_W + k * CHUNK;
        uint32_t ah[2][4];
        LDSM4(ah[0], aH[0] + k * 4096);
        LDSM4(ah[1], aH[1] + k * 4096);
        uint32_t b[2 * NT];
        if (NT == 9) {
            LDSM4(b, wb + bOff[0]); LDSM4(b + 4, wb + bOff[1]);
            LDSM4(b + 8, wb + bOff[2]); LDSM4(b + 12, wb + bOff[3]);
            LDSM2(b + 16, wb + bOff[4]);
        } else {
            LDSM4(b, wb + bOff[0]); LDSM4(b + 4, wb + bOff[1]);
        }
        #pragma unroll
        for (int j = 0; j < NT; ++j) { mma_f16(acc[j], ah[0], b + 2 * j); mma_f16(acc[NT + j], ah[1], b + 2 * j); }
    }
}

// ---------------- relu epilogue: write fp16 X tile for next stage ----------------
__device__ __forceinline__ void epi_relu(char* smem, float (*acc)[4], const float* bias,
                                         int m0, int nbase, int lane) {
    char* xh = smem + OFF_X;
    const int grp = lane >> 2;
    const int c0 = 2 * (lane & 3);
    #pragma unroll
    for (int mt = 0; mt < 2; ++mt)
    #pragma unroll
    for (int j = 0; j < 9; ++j) {
        int n0 = nbase + j * 8 + c0;
        float bv0 = bias ? bias[n0] : 0.f;
        float bv1 = bias ? bias[n0 + 1] : 0.f;
        int ks = n0 >> 4, kk = n0 & 15;
        #pragma unroll
        for (int rp = 0; rp < 2; ++rp) {
            int row = m0 + mt * 64 + grp + rp * 8;
            float v0 = fmaxf(acc[mt * 9 + j][rp * 2 + 0] + bv0, 0.f);
            float v1 = fmaxf(acc[mt * 9 + j][rp * 2 + 1] + bv1, 0.f);
            __half2 hp; hp.x = __float2half(v0); hp.y = __float2half(v1);
            *(__half2*)(xh + x_off(ks, row, kk)) = hp;
        }
    }
}

// ---------------- bulk stage-weight loader ----------------
__device__ __forceinline__ void load_weights(uint32_t su, const char* Wg, int bytes, int tid) {
    for (int off = tid * 16; off < bytes; off += 4096)
        CP16(su + OFF_W + off, Wg + off);
    CP_COMMIT();
}

// ---------------- main ----------------
__global__ void __launch_bounds__(256, 2)
mlp_main_kernel(const float* __restrict__ P,
                const float* __restrict__ b2, const float* __restrict__ b3,
                float* __restrict__ out) {
    const int mc = g_map[blockIdx.x];
    const int t = mc >> 8;
    const int c = mc & 255;
    const int s0 = t + 4 * c;

    extern __shared__ char smem[];
    uint32_t su = smem_u32(smem);
    const int tid = threadIdx.x;
    float* sB2 = (float*)(smem + OFF_B2);
    float* sB3 = (float*)(smem + OFF_B3);
    int* sRed = (int*)(smem + OFF_RED);    // ALIASES X tile; valid only after stage C

    // issue stage-A weight load first (hides behind feature build)
    load_weights(su, (const char*)g_W1h, WBYTES_A, tid);

    for (int i = tid; i < 144; i += 256) sB2[i] = (i < H_) ? b2[i] : 0.f;
    if (tid < 64) sB3[tid] = b3[tid];

    // feature build: rows r = sl*32+bb (sl 0..3); K cols [0,128) = running max, fp16
    {
        int d = tid & 127, half = tid >> 7;
        char* xh = smem + OFF_X;
        int ksM = d >> 4, kk = d & 15;
        for (int bb = half * 16; bb < half * 16 + 16; ++bb) {
            float run = (c > 0) ? g_pre4[((t * 32 + (c - 1)) * BB_ + bb) * D_ + d] : -3.4e38f;
            #pragma unroll
            for (int sl = 0; sl < 4; ++sl) {
                int s = s0 + sl;
                if (s < T_) run = fmaxf(run, P[(bb * T_ + s) * D_ + d]);
                int row = sl * 32 + bb;
                *(__half*)(xh + x_off(ksM, row, kk)) = __float2half(run);
            }
        }
    }
    CP_WAIT0();
    __syncthreads();

    const int wid = tid >> 5, lane = tid & 31;
    const int mq = wid >> 1, nq = wid & 1;      // 4 m-quads x 2 n-halves; m-tiles at m0, m0+64
    const int m0 = mq * 16;
    const int grp = lane >> 2, c0 = 2 * (lane & 3);

    // per-lane ldmatrix addresses
    uint32_t aH[2], bAB[5], bC[2];
    {
        int l15 = lane & 15, chnk = lane >> 4;
        #pragma unroll
        for (int mt = 0; mt < 2; ++mt) {
            int row = m0 + mt * 64 + l15;
            int phys = chnk ^ ((row >> 2) & 1);
            aH[mt] = su + OFF_X + row * 32 + phys * 16;
        }
        int l7 = lane & 7, kh = (lane >> 3) & 1, pr = (lane >> 4) & 1;
        #pragma unroll
        for (int i = 0; i < 4; ++i)
            bAB[i] = (uint32_t)((nq * 72 + 16 * i + pr * 8 + l7) * 48 + kh * 16);
        bAB[4] = (uint32_t)((nq * 72 + 64 + l7) * 48 + kh * 16);
        #pragma unroll
        for (int i = 0; i < 2; ++i)
            bC[i] = (uint32_t)((nq * 32 + 16 * i + pr * 8 + l7) * 48 + kh * 16);
    }

    float acc[18][4];

    // Stage A: acc preloaded from PW (P-part + b1, exact fp32), K=128 M-part only
    #pragma unroll
    for (int mt = 0; mt < 2; ++mt) {
        int r_lo = m0 + mt * 64 + grp, r_hi = r_lo + 8;
        int s_lo = min(s0 + (r_lo >> 5), T_ - 1), s_hi = min(s0 + (r_hi >> 5), T_ - 1);
        const float* pwlo = g_PW + (s_lo * BB_ + (r_lo & 31)) * 144;
        const float* pwhi = g_PW + (s_hi * BB_ + (r_hi & 31)) * 144;
        #pragma unroll
        for (int j = 0; j < 9; ++j) {
            int n0 = nq * 72 + j * 8 + c0;
            float2 vlo = *(const float2*)(pwlo + n0);
            float2 vhi = *(const float2*)(pwhi + n0);
            acc[mt * 9 + j][0] = vlo.x; acc[mt * 9 + j][1] = vlo.y;
            acc[mt * 9 + j][2] = vhi.x; acc[mt * 9 + j][3] = vhi.y;
        }
    }
    gemm_stage<8, 9, WCH_AB>(su, acc, aH, bAB);
    __syncthreads();                          // all warps done reading W-A and X-A
    load_weights(su, (const char*)g_W2h, WBYTES_B, tid);   // hide behind epi A
    epi_relu(smem, acc, (const float*)0, m0, nq * 72, lane);
    CP_WAIT0();
    __syncthreads();

    // Stage B: K=144 (9 ksteps), N=144
    #pragma unroll
    for (int i = 0; i < 18; ++i) { acc[i][0] = acc[i][1] = acc[i][2] = acc[i][3] = 0.f; }
    gemm_stage<9, 9, WCH_AB>(su, acc, aH, bAB);
    __syncthreads();
    load_weights(su, (const char*)g_W3h, WBYTES_C, tid);   // hide behind epi B
    epi_relu(smem, acc, sB2, m0, nq * 72, lane);
    CP_WAIT0();
    __syncthreads();

    // Stage C: K=144 (9 ksteps), N=64 (acc[0..7] = 2 m-tiles x 4 n-tiles)
    #pragma unroll
    for (int i = 0; i < 8; ++i) { acc[i][0] = acc[i][1] = acc[i][2] = acc[i][3] = 0.f; }
    gemm_stage<9, 4, WCH_C>(su, acc, aH, bC);

    // X tile is dead now; init the aliased reduction buffer, then reduce
    __syncthreads();
    for (int i = tid; i < BB_ * O_; i += 256) sRed[i] = 0;
    __syncthreads();

    // final epilogue: sigmoid + max reduce
    {
        #pragma unroll
        for (int mt = 0; mt < 2; ++mt)
        #pragma unroll
        for (int rp = 0; rp < 2; ++rp) {
            int row = m0 + mt * 64 + grp + rp * 8;
            int sl = row >> 5, bb = row & 31;
            if (s0 + sl < T_) {
                #pragma unroll
                for (int j = 0; j < 4; ++j) {
                    int n0 = nq * 32 + j * 8 + c0;
                    float y0 = 1.f / (1.f + __expf(-5.f * (acc[mt * 4 + j][rp * 2 + 0] + sB3[n0])));
                    float y1 = 1.f / (1.f + __expf(-5.f * (acc[mt * 4 + j][rp * 2 + 1] + sB3[n0 + 1])));
                    atomicMax(&sRed[bb * O_ + n0], __float_as_int(y0));
                    atomicMax(&sRed[bb * O_ + n0 + 1], __float_as_int(y1));
                }
            }
        }
    }
    __syncthreads();
    for (int i = tid; i < BB_ * O_; i += 256) {
        int bb = i >> 6, o = i & 63;
        atomicMax((int*)(out + (bb * T_ + t) * O_ + o), sRed[i]);
    }
}

// ---------------- launch ----------------
extern "C" void kernel_launch(void* const* d_in, const int* in_sizes, int n_in,
                              void* d_out, int out_size) {
    const float* P  = (const float*)d_in[0];
    const float* W1 = (const float*)d_in[1];
    const float* b1 = (const float*)d_in[2];
    const float* W2 = (const float*)d_in[3];
    const float* b2 = (const float*)d_in[4];
    const float* W3 = (const float*)d_in[5];
    const float* b3 = (const float*)d_in[6];
    float* out = (float*)d_out;

    cudaFuncSetAttribute(mlp_main_kernel, cudaFuncAttributeMaxDynamicSharedMemorySize, SMEM_TOTAL);
    cudaFuncSetAttribute(compute_pw_kernel, cudaFuncAttributeMaxDynamicSharedMemorySize, PW_SMEM);

    prep_weights<<<(9 * 144 * NSTRIDE + 255) / 256, 256>>>(W1, W2, W3);
    build_map<<<1, 128>>>();
    compute_pre_kernel<<<(T_ * BB_ * D_) / 256, 256>>>(P, out);
    compute_pw_kernel<<<T_, 256, PW_SMEM>>>(P, W1, b1);
    mlp_main_kernel<<<NBLK, 256, SMEM_TOTAL>>>(P, b2, b3, out);
}

// round 12
// speedup vs baseline: 6.2866x; 1.1177x over previous
#include <cuda_runtime.h>
#include <cuda_fp16.h>
#include <math.h>
#include <stdint.h>

#define BB_ 32
#define T_ 128
#define D_ 128
#define H_ 132
#define O_ 64

#define NSTRIDE 24                    // fp16 per n-row (48B): [16 k-vals][8B pad] -> ldmatrix conflict-free
#define WCH_AB (144 * 48)             // 6912 B per k-step chunk (N=144)
#define WCH_C  (64 * 48)              // 3072 B per k-step chunk (N=64)
#define WBYTES_A (8 * WCH_AB)         // 55296
#define WBYTES_B (9 * WCH_AB)         // 62208
#define WBYTES_C (9 * WCH_C)          // 27648

// ---------------- main-kernel SMEM layout ----------------
#define OFF_X   0                     // 9 ksteps x 128 rows x 32B = 36864
#define OFF_W   36864                 // whole-stage weights, max 62208 -> 99072
#define OFF_B2  99072                 // 144 floats -> 99648
#define OFF_B3  99648                 // 64 floats  -> 99904
#define OFF_RED OFF_X                 // sRed (8192B) ALIASES X tile; used only after stage C
#define SMEM_TOTAL 99904              // x2 blocks = 199808 < 228KB/SM

// ---------------- PW-kernel SMEM layout (shares OFF_W with gemm_stage) ----------------
#define PWK_XL  92160                 // Xl (32768) -> 124928   (Xh at 0, W at OFF_W=36864..92160)
#define PWK_B1  124928                // 144 floats -> 125504
#define PWK_SMEM 125504

#define NBLK 2112                     // sum_t ceil((128-t)/4)

// ---------------- device scratch ----------------
__device__ float g_pre4[T_ * 32 * BB_ * D_];   // [t][c][bb][d] prefix max over [t, t+4(c+1))
__device__ float g_PW[T_ * BB_ * 144];         // [s][bb][n]: P(s,bb)·W1[128:256] + b1
__device__ __half g_W1h[8 * 144 * NSTRIDE];    // [kstep][n][24], W1 rows 0..127 (M part), fp16
__device__ __half g_W1pw[8 * 144 * NSTRIDE];   // [kstep][n][24], W1 rows 128..255 (P part), fp16
__device__ __half g_W2h[9 * 144 * NSTRIDE];
__device__ __half g_W3h[9 * 64 * NSTRIDE];
__device__ int g_map[NBLK];                    // packed (t<<8)|c

// ---------------- asm helpers ----------------
__device__ __forceinline__ void mma_f16(float d[4], const uint32_t a[4], const uint32_t b[2]) {
    asm volatile("mma.sync.aligned.m16n8k16.row.col.f32.f16.f16.f32 "
                 "{%0,%1,%2,%3}, {%4,%5,%6,%7}, {%8,%9}, {%0,%1,%2,%3};"
                 : "+f"(d[0]), "+f"(d[1]), "+f"(d[2]), "+f"(d[3])
                 : "r"(a[0]), "r"(a[1]), "r"(a[2]), "r"(a[3]), "r"(b[0]), "r"(b[1]));
}
__device__ __forceinline__ uint32_t smem_u32(const void* p) {
    uint32_t a;
    asm("{ .reg .u64 t; cvta.to.shared.u64 t, %1; cvt.u32.u64 %0, t; }" : "=r"(a) : "l"(p));
    return a;
}
#define CP16(dst, src) asm volatile("cp.async.ca.shared.global [%0], [%1], 16;" :: "r"(dst), "l"(src) : "memory")
#define CP_COMMIT()    asm volatile("cp.async.commit_group;" ::: "memory")
#define CP_WAIT0()     asm volatile("cp.async.wait_group 0;" ::: "memory")
#define LDSM4(r, a) asm volatile("ldmatrix.sync.aligned.m8n8.x4.shared.b16 {%0,%1,%2,%3}, [%4];" \
    : "=r"((r)[0]), "=r"((r)[1]), "=r"((r)[2]), "=r"((r)[3]) : "r"(a))
#define LDSM2(r, a) asm volatile("ldmatrix.sync.aligned.m8n8.x2.shared.b16 {%0,%1}, [%2];" \
    : "=r"((r)[0]), "=r"((r)[1]) : "r"(a))

// X element address with 16B-half swizzle (ldmatrix conflict-free); 128 rows/kstep
__device__ __forceinline__ int x_off(int ks, int row, int kk) {
    int phys = (kk >> 3) ^ ((row >> 2) & 1);
    return ks * 4096 + row * 32 + phys * 16 + (kk & 7) * 2;
}

// ---------------- prep: fp16 weights, N padded to 144, 48B n-stride ----------------
__global__ void prep_weights(const float* __restrict__ W1, const float* __restrict__ W2,
                             const float* __restrict__ W3) {
    int i = blockIdx.x * blockDim.x + threadIdx.x;
    if (i < 8 * 144 * NSTRIDE) {
        int ks = i / (144 * NSTRIDE), r = i % (144 * NSTRIDE);
        int n = r / NSTRIDE, kk = r % NSTRIDE;
        __half o = __float2half(0.f), o2 = o;
        if (kk < 16 && n < H_) {
            o  = __float2half(W1[(ks * 16 + kk) * H_ + n]);
            o2 = __float2half(W1[(128 + ks * 16 + kk) * H_ + n]);
        }
        g_W1h[i] = o;
        g_W1pw[i] = o2;
    }
    if (i < 9 * 144 * NSTRIDE) {
        int ks = i / (144 * NSTRIDE), r = i % (144 * NSTRIDE);
        int n = r / NSTRIDE, kk = r % NSTRIDE;
        int k = ks * 16 + kk;
        __half o = __float2half(0.f);
        if (kk < 16 && n < H_ && k < H_) o = __float2half(W2[k * H_ + n]);
        g_W2h[i] = o;
    }
    if (i < 9 * 64 * NSTRIDE) {
        int ks = i / (64 * NSTRIDE), r = i % (64 * NSTRIDE);
        int n = r / NSTRIDE, kk = r % NSTRIDE;
        int k = ks * 16 + kk;
        __half o = __float2half(0.f);
        if (kk < 16 && k < H_) o = __float2half(W3[k * O_ + n]);
        g_W3h[i] = o;
    }
}

// ---------------- block map: linear index -> (t, c) ----------------
__global__ void build_map() {
    int t = threadIdx.x;               // 128 threads
    int start = 0;
    for (int u = 0; u < t; ++u) start += (131 - u) >> 2;
    int nch = (131 - t) >> 2;
    for (int c2 = 0; c2 < nch; ++c2) g_map[start + c2] = (t << 8) | c2;
}

// ---------------- prefix max at 4-step boundaries (+ out init folded in) ----------------
__global__ void compute_pre_kernel(const float* __restrict__ P, float* __restrict__ out) {
    int idx = blockIdx.x * blockDim.x + threadIdx.x;
    if (idx < BB_ * T_ * O_) out[idx] = 0.f;
    int t = idx >> 12, bb = (idx >> 7) & 31, d = idx & 127;
    const float* Pp = P + bb * (T_ * D_) + d;
    float run = -3.4e38f;
    for (int s = t; s < T_; ++s) {
        run = fmaxf(run, Pp[s * D_]);
        int m = s - t + 1;
        if ((m & 3) == 0) {
            int ci = (m >> 2) - 1;
            if (ci < 32) g_pre4[((t * 32 + ci) * BB_ + bb) * D_ + d] = run;
        }
    }
}

// ---------------- barrier-free GEMM stage: whole-stage weights resident in smem ----------------
template <int K16, int NT, int CHUNK>
__device__ __forceinline__ void gemm_stage(uint32_t su, float (*acc)[4],
                                           const uint32_t aH[2], const uint32_t* bOff) {
    #pragma unroll
    for (int k = 0; k < K16; ++k) {
        uint32_t wb = su + OFF_W + k * CHUNK;
        uint32_t ah[2][4];
        LDSM4(ah[0], aH[0] + k * 4096);
        LDSM4(ah[1], aH[1] + k * 4096);
        uint32_t b[2 * NT];
        if (NT == 9) {
            LDSM4(b, wb + bOff[0]); LDSM4(b + 4, wb + bOff[1]);
            LDSM4(b + 8, wb + bOff[2]); LDSM4(b + 12, wb + bOff[3]);
            LDSM2(b + 16, wb + bOff[4]);
        } else {
            LDSM4(b, wb + bOff[0]); LDSM4(b + 4, wb + bOff[1]);
        }
        #pragma unroll
        for (int j = 0; j < NT; ++j) { mma_f16(acc[j], ah[0], b + 2 * j); mma_f16(acc[NT + j], ah[1], b + 2 * j); }
    }
}

// ---------------- bulk stage-weight loader ----------------
__device__ __forceinline__ void load_weights(uint32_t su, const char* Wg, int bytes, int tid) {
    for (int off = tid * 16; off < bytes; off += 4096)
        CP16(su + OFF_W + off, Wg + off);
    CP_COMMIT();
}

// ---------------- PW via tensor cores: g_PW[s][bb][n] = P·W1[128:256] + b1 ----------------
// 32 blocks, block = 4 s-values x 32 bb = 128 rows; 2-pass Xh+Xl fp16 split.
__global__ void __launch_bounds__(256, 1)
compute_pw_mma(const float* __restrict__ P, const float* __restrict__ b1) {
    const int s4 = blockIdx.x;          // s = s4*4 + sl
    extern __shared__ char smem[];
    uint32_t su = smem_u32(smem);
    const int tid = threadIdx.x;
    float* sB1 = (float*)(smem + PWK_B1);

    load_weights(su, (const char*)g_W1pw, WBYTES_A, tid);
    for (int i = tid; i < 144; i += 256) sB1[i] = (i < H_) ? b1[i] : 0.f;

    // X build: hi/lo fp16 of P, vectorized
    {
        int p = tid & 63, g = tid >> 6;
        int d0 = 2 * p, ks = d0 >> 4, kk = d0 & 15;
        char* xh = smem;
        char* xl = smem + PWK_XL;
        for (int b8 = 0; b8 < 8; ++b8) {
            int bb = g * 8 + b8;
            #pragma unroll
            for (int sl = 0; sl < 4; ++sl) {
                int s = s4 * 4 + sl;
                float2 pv = *(const float2*)&P[(bb * T_ + s) * D_ + d0];
                int row = sl * 32 + bb;
                int ph = (kk >> 3) ^ ((row >> 2) & 1);
                int off = ks * 4096 + row * 32 + ph * 16 + (kk & 7) * 2;
                __half2 h, l;
                h.x = __float2half(pv.x); h.y = __float2half(pv.y);
                l.x = __float2half(pv.x - __half2float(h.x));
                l.y = __float2half(pv.y - __half2float(h.y));
                *(__half2*)(xh + off) = h;
                *(__half2*)(xl + off) = l;
            }
        }
    }
    CP_WAIT0();
    __syncthreads();

    const int wid = tid >> 5, lane = tid & 31;
    const int mq = wid >> 1, nq = wid & 1;
    const int m0 = mq * 16;
    const int grp = lane >> 2, c0 = 2 * (lane & 3);

    uint32_t aH[2], aL[2], bAB[5];
    {
        int l15 = lane & 15, chnk = lane >> 4;
        #pragma unroll
        for (int mt = 0; mt < 2; ++mt) {
            int row = m0 + mt * 64 + l15;
            int phys = chnk ^ ((row >> 2) & 1);
            aH[mt] = su + row * 32 + phys * 16;
            aL[mt] = aH[mt] + PWK_XL;
        }
        int l7 = lane & 7, kh = (lane >> 3) & 1, pr = (lane >> 4) & 1;
        #pragma unroll
        for (int i = 0; i < 4; ++i)
            bAB[i] = (uint32_t)((nq * 72 + 16 * i + pr * 8 + l7) * 48 + kh * 16);
        bAB[4] = (uint32_t)((nq * 72 + 64 + l7) * 48 + kh * 16);
    }

    float acc[18][4];
    #pragma unroll
    for (int i = 0; i < 18; ++i) { acc[i][0] = acc[i][1] = acc[i][2] = acc[i][3] = 0.f; }
    gemm_stage<8, 9, WCH_AB>(su, acc, aH, bAB);   // hi pass
    gemm_stage<8, 9, WCH_AB>(su, acc, aL, bAB);   // lo pass

    // epilogue: + b1, write fp32 PW
    #pragma unroll
    for (int mt = 0; mt < 2; ++mt)
    #pragma unroll
    for (int rp = 0; rp < 2; ++rp) {
        int row = m0 + mt * 64 + grp + rp * 8;
        int sl = row >> 5, bb = row & 31;
        int s = s4 * 4 + sl;
        #pragma unroll
        for (int j = 0; j < 9; ++j) {
            int n0 = nq * 72 + j * 8 + c0;
            float2 v;
            v.x = acc[mt * 9 + j][rp * 2 + 0] + sB1[n0];
            v.y = acc[mt * 9 + j][rp * 2 + 1] + sB1[n0 + 1];
            *(float2*)&g_PW[(s * BB_ + bb) * 144 + n0] = v;
        }
    }
}

// ---------------- relu epilogue: write fp16 X tile for next stage ----------------
__device__ __forceinline__ void epi_relu(char* smem, float (*acc)[4], const float* bias,
                                         int m0, int nbase, int lane) {
    char* xh = smem + OFF_X;
    const int grp = lane >> 2;
    const int c0 = 2 * (lane & 3);
    #pragma unroll
    for (int mt = 0; mt < 2; ++mt)
    #pragma unroll
    for (int j = 0; j < 9; ++j) {
        int n0 = nbase + j * 8 + c0;
        float bv0 = bias ? bias[n0] : 0.f;
        float bv1 = bias ? bias[n0 + 1] : 0.f;
        int ks = n0 >> 4, kk = n0 & 15;
        #pragma unroll
        for (int rp = 0; rp < 2; ++rp) {
            int row = m0 + mt * 64 + grp + rp * 8;
            float v0 = fmaxf(acc[mt * 9 + j][rp * 2 + 0] + bv0, 0.f);
            float v1 = fmaxf(acc[mt * 9 + j][rp * 2 + 1] + bv1, 0.f);
            __half2 hp; hp.x = __float2half(v0); hp.y = __float2half(v1);
            *(__half2*)(xh + x_off(ks, row, kk)) = hp;
        }
    }
}

// ---------------- main ----------------
__global__ void __launch_bounds__(256, 2)
mlp_main_kernel(const float* __restrict__ P,
                const float* __restrict__ b2, const float* __restrict__ b3,
                float* __restrict__ out) {
    const int mc = g_map[blockIdx.x];
    const int t = mc >> 8;
    const int c = mc & 255;
    const int s0 = t + 4 * c;

    extern __shared__ char smem[];
    uint32_t su = smem_u32(smem);
    const int tid = threadIdx.x;
    float* sB2 = (float*)(smem + OFF_B2);
    float* sB3 = (float*)(smem + OFF_B3);
    int* sRed = (int*)(smem + OFF_RED);    // ALIASES X tile; valid only after stage C

    // issue stage-A weight load first (hides behind feature build)
    load_weights(su, (const char*)g_W1h, WBYTES_A, tid);

    for (int i = tid; i < 144; i += 256) sB2[i] = (i < H_) ? b2[i] : 0.f;
    if (tid < 64) sB3[tid] = b3[tid];

    // feature build (vectorized): rows r = sl*32+bb; K cols [0,128) = running max, fp16
    {
        int p = tid & 63, g = tid >> 6;
        int d0 = 2 * p, ks = d0 >> 4, kk = d0 & 15;
        char* xh = smem + OFF_X;
        for (int b8 = 0; b8 < 8; ++b8) {
            int bb = g * 8 + b8;
            float2 run2;
            if (c > 0) run2 = *(const float2*)&g_pre4[((t * 32 + (c - 1)) * BB_ + bb) * D_ + d0];
            else { run2.x = -3.4e38f; run2.y = -3.4e38f; }
            #pragma unroll
            for (int sl = 0; sl < 4; ++sl) {
                int s = s0 + sl;
                if (s < T_) {
                    float2 pv = *(const float2*)&P[(bb * T_ + s) * D_ + d0];
                    run2.x = fmaxf(run2.x, pv.x);
                    run2.y = fmaxf(run2.y, pv.y);
                }
                int row = sl * 32 + bb;
                int ph = (kk >> 3) ^ ((row >> 2) & 1);
                int off = ks * 4096 + row * 32 + ph * 16 + (kk & 7) * 2;
                __half2 hp; hp.x = __float2half(run2.x); hp.y = __float2half(run2.y);
                *(__half2*)(xh + off) = hp;
            }
        }
    }
    CP_WAIT0();
    __syncthreads();

    const int wid = tid >> 5, lane = tid & 31;
    const int mq = wid >> 1, nq = wid & 1;      // 4 m-quads x 2 n-halves; m-tiles at m0, m0+64
    const int m0 = mq * 16;
    const int grp = lane >> 2, c0 = 2 * (lane & 3);

    // per-lane ldmatrix addresses
    uint32_t aH[2], bAB[5], bC[2];
    {
        int l15 = lane & 15, chnk = lane >> 4;
        #pragma unroll
        for (int mt = 0; mt < 2; ++mt) {
            int row = m0 + mt * 64 + l15;
            int phys = chnk ^ ((row >> 2) & 1);
            aH[mt] = su + OFF_X + row * 32 + phys * 16;
        }
        int l7 = lane & 7, kh = (lane >> 3) & 1, pr = (lane >> 4) & 1;
        #pragma unroll
        for (int i = 0; i < 4; ++i)
            bAB[i] = (uint32_t)((nq * 72 + 16 * i + pr * 8 + l7) * 48 + kh * 16);
        bAB[4] = (uint32_t)((nq * 72 + 64 + l7) * 48 + kh * 16);
        #pragma unroll
        for (int i = 0; i < 2; ++i)
            bC[i] = (uint32_t)((nq * 32 + 16 * i + pr * 8 + l7) * 48 + kh * 16);
    }

    float acc[18][4];

    // Stage A: acc preloaded from PW (P-part + b1), K=128 M-part only
    #pragma unroll
    for (int mt = 0; mt < 2; ++mt) {
        int r_lo = m0 + mt * 64 + grp, r_hi = r_lo + 8;
        int s_lo = min(s0 + (r_lo >> 5), T_ - 1), s_hi = min(s0 + (r_hi >> 5), T_ - 1);
        const float* pwlo = g_PW + (s_lo * BB_ + (r_lo & 31)) * 144;
        const float* pwhi = g_PW + (s_hi * BB_ + (r_hi & 31)) * 144;
        #pragma unroll
        for (int j = 0; j < 9; ++j) {
            int n0 = nq * 72 + j * 8 + c0;
            float2 vlo = *(const float2*)(pwlo + n0);
            float2 vhi = *(const float2*)(pwhi + n0);
            acc[mt * 9 + j][0] = vlo.x; acc[mt * 9 + j][1] = vlo.y;
            acc[mt * 9 + j][2] = vhi.x; acc[mt * 9 + j][3] = vhi.y;
        }
    }
    gemm_stage<8, 9, WCH_AB>(su, acc, aH, bAB);
    __syncthreads();                          // all warps done reading W-A and X-A
    load_weights(su, (const char*)g_W2h, WBYTES_B, tid);   // hide behind epi A
    epi_relu(smem, acc, (const float*)0, m0, nq * 72, lane);
    CP_WAIT0();
    __syncthreads();

    // Stage B: K=144 (9 ksteps), N=144
    #pragma unroll
    for (int i = 0; i < 18; ++i) { acc[i][0] = acc[i][1] = acc[i][2] = acc[i][3] = 0.f; }
    gemm_stage<9, 9, WCH_AB>(su, acc, aH, bAB);
    __syncthreads();
    load_weights(su, (const char*)g_W3h, WBYTES_C, tid);   // hide behind epi B
    epi_relu(smem, acc, sB2, m0, nq * 72, lane);
    CP_WAIT0();
    __syncthreads();

    // Stage C: K=144 (9 ksteps), N=64 (acc[0..7] = 2 m-tiles x 4 n-tiles)
    #pragma unroll
    for (int i = 0; i < 8; ++i) { acc[i][0] = acc[i][1] = acc[i][2] = acc[i][3] = 0.f; }
    gemm_stage<9, 4, WCH_C>(su, acc, aH, bC);

    // X tile is dead now; init the aliased reduction buffer, then reduce
    __syncthreads();
    for (int i = tid; i < BB_ * O_; i += 256) sRed[i] = 0;
    __syncthreads();

    // final epilogue: sigmoid + max reduce
    {
        #pragma unroll
        for (int mt = 0; mt < 2; ++mt)
        #pragma unroll
        for (int rp = 0; rp < 2; ++rp) {
            int row = m0 + mt * 64 + grp + rp * 8;
            int sl = row >> 5, bb = row & 31;
            if (s0 + sl < T_) {
                #pragma unroll
                for (int j = 0; j < 4; ++j) {
                    int n0 = nq * 32 + j * 8 + c0;
                    float y0 = 1.f / (1.f + __expf(-5.f * (acc[mt * 4 + j][rp * 2 + 0] + sB3[n0])));
                    float y1 = 1.f / (1.f + __expf(-5.f * (acc[mt * 4 + j][rp * 2 + 1] + sB3[n0 + 1])));
                    atomicMax(&sRed[bb * O_ + n0], __float_as_int(y0));
                    atomicMax(&sRed[bb * O_ + n0 + 1], __float_as_int(y1));
                }
            }
        }
    }
    __syncthreads();
    for (int i = tid; i < BB_ * O_; i += 256) {
        int bb = i >> 6, o = i & 63;
        atomicMax((int*)(out + (bb * T_ + t) * O_ + o), sRed[i]);
    }
}

// ---------------- launch ----------------
extern "C" void kernel_launch(void* const* d_in, const int* in_sizes, int n_in,
                              void* d_out, int out_size) {
    const float* P  = (const float*)d_in[0];
    const float* W1 = (const float*)d_in[1];
    const float* b1 = (const float*)d_in[2];
    const float* W2 = (const float*)d_in[3];
    const float* b2 = (const float*)d_in[4];
    const float* W3 = (const float*)d_in[5];
    const float* b3 = (const float*)d_in[6];
    float* out = (float*)d_out;

    cudaFuncSetAttribute(mlp_main_kernel, cudaFuncAttributeMaxDynamicSharedMemorySize, SMEM_TOTAL);
    cudaFuncSetAttribute(compute_pw_mma, cudaFuncAttributeMaxDynamicSharedMemorySize, PWK_SMEM);

    prep_weights<<<(9 * 144 * NSTRIDE + 255) / 256, 256>>>(W1, W2, W3);
    build_map<<<1, 128>>>();
    compute_pre_kernel<<<(T_ * BB_ * D_) / 256, 256>>>(P, out);
    compute_pw_mma<<<T_ / 4, 256, PWK_SMEM>>>(P, b1);
    mlp_main_kernel<<<NBLK, 256, SMEM_TOTAL>>>(P, b2, b3, out);
}